// round 8
// baseline (speedup 1.0000x reference)
#include <cuda_runtime.h>
#include <math.h>

#define Tn  4096
#define INn 512
#define Kn  64
#define Vn  64
#define Hn  4096

// ---------------- scratch (device globals; no cudaMalloc allowed) -----------
__device__ float g_k  [Tn * Kn];
__device__ float g_q  [Tn * Kn];
__device__ float g_v  [Tn * Vn];
__device__ float g_att[Tn * Vn];
__device__ float g_h1 [Tn * Hn];   // h1, later reused for h3
__device__ float g_h2 [Tn * Hn];

// ---------------- activations ----------------------------------------------
// mish via algebraic form (fast-math safe): with u=e^x,
// tanh(softplus(x)) = u(u+2)/(u(u+2)+2); accurate ~1e-6 under fast math.
__device__ __forceinline__ float mishf(float x) {
    if (x > 20.f) return x;           // 2/w < 1e-17: tanh term == 1 in fp32
    float u = expf(x);
    float w = u * (u + 2.f);
    return x * w / (w + 2.f);         // x<-88: u=0 -> returns 0 (correct limit)
}

// ---------------- generic NT SGEMM: C[M,N] = A[M,Kd] * B[N,Kd]^T ------------
// Exact fp32 operands and accumulation (reference is exact-fp32 numpy).
// EPI: 0 = C = acc + bias ; 1 = C = mish(acc + bias)
//      2 = C = phi(acc)   ; 3 = C += acc + bias
template <int EPI>
__global__ __launch_bounds__(256)
void sgemm_nt(const float* __restrict__ A, const float* __restrict__ B,
              const float* __restrict__ bias, float* __restrict__ C,
              int M, int N, int Kd)
{
    __shared__ float As[8][128];
    __shared__ float Bs[8][128];

    const int tid = threadIdx.x;
    const int m0  = blockIdx.y * 128;
    const int n0  = blockIdx.x * 128;
    const int tx  = tid & 15;   // 0..15 -> 8 cols each
    const int ty  = tid >> 4;   // 0..15 -> 8 rows each

    float acc[8][8];
#pragma unroll
    for (int i = 0; i < 8; i++)
#pragma unroll
        for (int j = 0; j < 8; j++) acc[i][j] = 0.f;

    const int lr = tid >> 1;        // 0..127 (tile row)
    const int lc = (tid & 1) * 4;   // 0 or 4 (k sub-offset)

    for (int k0 = 0; k0 < Kd; k0 += 8) {
        // M is always a multiple of 128 in this problem -> no A row guard.
        float4 av = *(const float4*)(A + (size_t)(m0 + lr) * Kd + k0 + lc);
        float4 bv4;
        if (n0 + lr < N)
            bv4 = *(const float4*)(B + (size_t)(n0 + lr) * Kd + k0 + lc);
        else
            bv4 = make_float4(0.f, 0.f, 0.f, 0.f);

        As[lc + 0][lr] = av.x;  As[lc + 1][lr] = av.y;
        As[lc + 2][lr] = av.z;  As[lc + 3][lr] = av.w;
        Bs[lc + 0][lr] = bv4.x; Bs[lc + 1][lr] = bv4.y;
        Bs[lc + 2][lr] = bv4.z; Bs[lc + 3][lr] = bv4.w;
        __syncthreads();

#pragma unroll
        for (int kk = 0; kk < 8; kk++) {
            float4 a0 = *(const float4*)&As[kk][ty * 8];
            float4 a1 = *(const float4*)&As[kk][ty * 8 + 4];
            float4 b0 = *(const float4*)&Bs[kk][tx * 8];
            float4 b1 = *(const float4*)&Bs[kk][tx * 8 + 4];
            float a[8] = {a0.x, a0.y, a0.z, a0.w, a1.x, a1.y, a1.z, a1.w};
            float b[8] = {b0.x, b0.y, b0.z, b0.w, b1.x, b1.y, b1.z, b1.w};
#pragma unroll
            for (int i = 0; i < 8; i++)
#pragma unroll
                for (int j = 0; j < 8; j++)
                    acc[i][j] = fmaf(a[i], b[j], acc[i][j]);
        }
        __syncthreads();
    }

#pragma unroll
    for (int j = 0; j < 8; j++) {
        int n = n0 + tx * 8 + j;
        if (n >= N) continue;
        float bs = bias ? bias[n] : 0.f;
#pragma unroll
        for (int i = 0; i < 8; i++) {
            int m = m0 + ty * 8 + i;
            float v = acc[i][j] + bs;
            float* cp = C + (size_t)m * N + n;
            if (EPI == 0)      *cp = v;
            else if (EPI == 1) *cp = mishf(v);
            else if (EPI == 2) *cp = (v > 0.f) ? (1.f + v) : expf(v);
            else               *cp += v;  // EPI == 3
        }
    }
}

// ---------------- segmented scan: s[t] = (start[t]?0:s[t-1]) + k_t (x) v_t --
// start is read as INT32: the harness materializes bool inputs as int32
// (its dtype list is float32/int32/bfloat16). Reading it as bytes (rounds
// 0-7) decoded a garbage reset pattern -> O(1)-wrong s,z and the invariant
// 1.328e-3 floor on hn (the attention branch is ~4e-4 of hn's norm).
__global__ __launch_bounds__(64)
void scan_kernel(const float* __restrict__ k, const float* __restrict__ v,
                 const int* __restrict__ start,
                 const float* __restrict__ s0, const float* __restrict__ z0,
                 float* __restrict__ out_s, float* __restrict__ out_z)
{
    __shared__ float vbuf[64 * 64];
    __shared__ float kbuf[64];
    __shared__ int   sbuf[64];

    const int i = blockIdx.x;
    const int j = threadIdx.x;

    float run  = s0[i * 64 + j];
    float zrun = z0[i];

    for (int t0 = 0; t0 < Tn; t0 += 64) {
#pragma unroll 4
        for (int tt = 0; tt < 64; tt++)
            vbuf[tt * 64 + j] = v[(size_t)(t0 + tt) * 64 + j];
        kbuf[j] = k[(size_t)(t0 + j) * 64 + i];
        sbuf[j] = start[t0 + j];
        __syncthreads();

        for (int tt = 0; tt < 64; tt++) {
            if (sbuf[tt]) { run = 0.f; zrun = 0.f; }
            float kt = kbuf[tt];
            run  = fmaf(kt, vbuf[tt * 64 + j], run);
            zrun += kt;
            out_s[(size_t)(t0 + tt) * 4096 + i * 64 + j] = run;
            if (j == 0) out_z[(size_t)(t0 + tt) * 64 + i] = zrun;
        }
        __syncthreads();
    }
}

// ---------------- attention output: numer / denom --------------------------
// numer[t,j] = sum_i s[t,i,j]*q[t,i]; denom[t] = max((sum_i z)*(sum_j q),1e-6)
__global__ __launch_bounds__(64)
void attn_kernel(const float* __restrict__ s, const float* __restrict__ z,
                 const float* __restrict__ q, float* __restrict__ outp)
{
    __shared__ float qs[64];
    __shared__ float zs[64];
    __shared__ float dsh;

    const int t = blockIdx.x, j = threadIdx.x;
    qs[j] = q[t * 64 + j];
    zs[j] = z[t * 64 + j];
    __syncthreads();
    if (j == 0) {
        float qsum = 0.f, zsum = 0.f;
        for (int i = 0; i < 64; i++) { qsum += qs[i]; zsum += zs[i]; }
        dsh = fmaxf(zsum * qsum, 1e-6f);
    }
    __syncthreads();

    float acc = 0.f;
    const float* sp = s + (size_t)t * 4096;
#pragma unroll 8
    for (int i = 0; i < 64; i++)
        acc = fmaf(sp[i * 64 + j], qs[i], acc);
    outp[t * 64 + j] = acc / dsh;
}

// ---------------- LayerNorm over H ------------------------------------------
__global__ __launch_bounds__(256)
void ln_kernel(const float* __restrict__ h, const float* __restrict__ g,
               const float* __restrict__ b, float* __restrict__ o)
{
    __shared__ float red[256];
    const int t = blockIdx.x, tid = threadIdx.x;
    const float* hp = h + (size_t)t * Hn;

    float loc[16];
    float sum = 0.f;
#pragma unroll
    for (int u = 0; u < 16; u++) { loc[u] = hp[tid + u * 256]; sum += loc[u]; }
    red[tid] = sum; __syncthreads();
    for (int s = 128; s > 0; s >>= 1) { if (tid < s) red[tid] += red[tid + s]; __syncthreads(); }
    float mu = red[0] * (1.f / Hn);
    __syncthreads();

    float sq = 0.f;
#pragma unroll
    for (int u = 0; u < 16; u++) { float d = loc[u] - mu; sq += d * d; }
    red[tid] = sq; __syncthreads();
    for (int s = 128; s > 0; s >>= 1) { if (tid < s) red[tid] += red[tid + s]; __syncthreads(); }
    float inv = rsqrtf(red[0] * (1.f / Hn) + 1e-5f);

#pragma unroll
    for (int u = 0; u < 16; u++) {
        int idx = tid + u * 256;
        o[(size_t)t * Hn + idx] = (loc[u] - mu) * inv * g[idx] + b[idx];
    }
}

// ---------------- launch ----------------------------------------------------
extern "C" void kernel_launch(void* const* d_in, const int* in_sizes, int n_in,
                              void* d_out, int out_size)
{
    const float* x     = (const float*)d_in[0];
    const float* s0    = (const float*)d_in[1];
    const float* z0    = (const float*)d_in[2];
    const int*   start = (const int*)d_in[3];   // bool materialized as int32
    // d_in[4] = next_done: dead input (never affects s, z, hn)
    const float* Wk    = (const float*)d_in[5];
    const float* Wq    = (const float*)d_in[6];
    const float* Wv    = (const float*)d_in[7];
    const float* bv    = (const float*)d_in[8];
    const float* Wskip = (const float*)d_in[9];
    const float* bskip = (const float*)d_in[10];
    const float* W1    = (const float*)d_in[11];
    const float* b1    = (const float*)d_in[12];
    const float* W2    = (const float*)d_in[13];
    const float* b2    = (const float*)d_in[14];
    const float* W3    = (const float*)d_in[15];
    const float* b3    = (const float*)d_in[16];
    const float* ln_g  = (const float*)d_in[17];
    const float* ln_b  = (const float*)d_in[18];

    float* out    = (float*)d_out;
    float* out_hn = out;                               // T*H
    float* out_s  = out + (size_t)Tn * Hn;             // T*K*V
    float* out_z  = out_s + (size_t)Tn * Kn * Vn;      // T*K

    float *gk, *gq, *gv, *gatt, *gh1, *gh2;
    cudaGetSymbolAddress((void**)&gk,  g_k);
    cudaGetSymbolAddress((void**)&gq,  g_q);
    cudaGetSymbolAddress((void**)&gv,  g_v);
    cudaGetSymbolAddress((void**)&gatt, g_att);
    cudaGetSymbolAddress((void**)&gh1, g_h1);
    cudaGetSymbolAddress((void**)&gh2, g_h2);

    dim3 blk(256);
    auto grd = [](int M, int N) { return dim3((N + 127) / 128, (M + 127) / 128); };

    // qkv projections (exact fp32)
    sgemm_nt<2><<<grd(Tn, Kn), blk>>>(x, Wk, nullptr, gk, Tn, Kn, INn);   // k = phi
    sgemm_nt<2><<<grd(Tn, Kn), blk>>>(x, Wq, nullptr, gq, Tn, Kn, INn);   // q = phi
    sgemm_nt<0><<<grd(Tn, Vn), blk>>>(x, Wv, bv, gv, Tn, Vn, INn);        // v + bv

    // segmented scan -> writes s, z directly into d_out regions
    scan_kernel<<<64, 64>>>(gk, gv, start, s0, z0, out_s, out_z);

    // attention readout
    attn_kernel<<<Tn, 64>>>(out_s, out_z, gq, gatt);

    // MLP (exact fp32)
    sgemm_nt<1><<<grd(Tn, Hn), blk>>>(gatt, W1, b1, gh1, Tn, Hn, Vn);     // mish
    sgemm_nt<1><<<grd(Tn, Hn), blk>>>(gh1, W2, b2, gh2, Tn, Hn, Hn);      // mish
    sgemm_nt<0><<<grd(Tn, Hn), blk>>>(gh2, W3, b3, gh1, Tn, Hn, Hn);      // h3
    sgemm_nt<3><<<grd(Tn, Hn), blk>>>(x, Wskip, bskip, gh1, Tn, Hn, INn); // += skip

    // LayerNorm -> hn
    ln_kernel<<<Tn, 256>>>(gh1, ln_g, ln_b, out_hn);
}

// round 10
// speedup vs baseline: 1.9727x; 1.9727x over previous
#include <cuda_runtime.h>
#include <cstdint>
#include <math.h>

#define Tn  4096
#define INn 512
#define Kn  64
#define Vn  64
#define Hn  4096

// ---------------- scratch (device globals; no cudaMalloc allowed) -----------
__device__ float g_k  [Tn * Kn];
__device__ float g_q  [Tn * Kn];
__device__ float g_v  [Tn * Vn];
__device__ float g_att[Tn * Vn];
__device__ float g_h1 [Tn * Hn];   // h1, later reused for h3
__device__ float g_h2 [Tn * Hn];

// ---------------- activations ----------------------------------------------
__device__ __forceinline__ float mishf(float x) {
    if (x > 20.f) return x;
    float u = expf(x);
    float w = u * (u + 2.f);
    return x * w / (w + 2.f);
}

// ======================= TF32 tensor-core GEMM ===============================
// C[M,N] = A[M,K] * W[N,K]^T (+bias). Used ONLY for the MLP GEMMs (W1/W2/W3):
// the whole attention->MLP branch is ~4e-4 of hn's magnitude, so TF32 noise
// lands at ~1.6e-7 on hn. qkv and skip stay exact fp32 (they feed s,z and the
// O(1) part of hn).
// Tiling: 128x128 block tile, KB=16, cp.async double buffer, 8 warps of 64x32,
// mma.sync.m16n8k8.tf32. smem [row][k] with row stride 20 floats: fragment
// loads hit banks (20g+tig)%32 = disjoint quads -> conflict-free.
#define GKB 16

__device__ __forceinline__ void cp_async16(uint32_t saddr, const void* gaddr) {
    asm volatile("cp.async.cg.shared.global [%0], [%1], 16;\n"
                 :: "r"(saddr), "l"(gaddr));
}
__device__ __forceinline__ void cp_commit() {
    asm volatile("cp.async.commit_group;\n");
}
template <int N>
__device__ __forceinline__ void cp_wait() {
    asm volatile("cp.async.wait_group %0;\n" :: "n"(N));
}

__device__ __forceinline__ void mma_tf32(float* d, const uint32_t* a, const uint32_t* b) {
    asm volatile(
        "mma.sync.aligned.m16n8k8.row.col.f32.tf32.tf32.f32 "
        "{%0,%1,%2,%3}, {%4,%5,%6,%7}, {%8,%9}, {%0,%1,%2,%3};\n"
        : "+f"(d[0]), "+f"(d[1]), "+f"(d[2]), "+f"(d[3])
        : "r"(a[0]), "r"(a[1]), "r"(a[2]), "r"(a[3]), "r"(b[0]), "r"(b[1]));
}

// EPI: 0 = C = acc + bias ; 1 = C = mish(acc + bias)
template <int EPI>
__global__ __launch_bounds__(256)
void gemm_tf32(const float* __restrict__ A, const float* __restrict__ W,
               const float* __restrict__ bias, float* __restrict__ C,
               int M, int N, int K)
{
    __shared__ float As[2][128][20];   // [m][k], 16 k used, stride 20
    __shared__ float Ws[2][128][20];   // [n][k]

    const int tid  = threadIdx.x;
    const int lane = tid & 31;
    const int wid  = tid >> 5;
    const int g    = lane >> 2;     // 0..7
    const int tig  = lane & 3;      // 0..3
    const int wm   = (wid & 1) * 64;
    const int wn   = (wid >> 1) * 32;
    const int m0   = blockIdx.y * 128;
    const int n0   = blockIdx.x * 128;

    // cp.async assignment: threads 0..127 fill As rows, 128..255 fill Ws rows
    const int ld_row = tid & 127;
    const bool is_a  = tid < 128;
    const float* gbase = is_a ? (A + (size_t)(m0 + ld_row) * K)
                              : (W + (size_t)(n0 + ld_row) * K);

    float acc[4][4][4];
#pragma unroll
    for (int mt = 0; mt < 4; mt++)
#pragma unroll
        for (int nt = 0; nt < 4; nt++)
#pragma unroll
            for (int r = 0; r < 4; r++) acc[mt][nt][r] = 0.f;

    auto issue = [&](int it) {
        int buf = it & 1;
        float* srow = is_a ? &As[buf][ld_row][0] : &Ws[buf][ld_row][0];
        uint32_t sa = (uint32_t)__cvta_generic_to_shared(srow);
        const float* gp = gbase + it * GKB;
#pragma unroll
        for (int ch = 0; ch < 4; ch++)
            cp_async16(sa + ch * 16, gp + ch * 4);
        cp_commit();
    };

    const int niter = K / GKB;
    issue(0);

    for (int it = 0; it < niter; it++) {
        if (it + 1 < niter) { issue(it + 1); cp_wait<1>(); }
        else                {               cp_wait<0>(); }
        __syncthreads();

        const int buf = it & 1;
#pragma unroll
        for (int kk = 0; kk < GKB; kk += 8) {
            uint32_t a[4][4], b[4][2];
#pragma unroll
            for (int mt = 0; mt < 4; mt++) {
                const float* r0 = &As[buf][wm + 16 * mt + g][kk + tig];
                const float* r1 = &As[buf][wm + 16 * mt + 8 + g][kk + tig];
                a[mt][0] = __float_as_uint(r0[0]);
                a[mt][1] = __float_as_uint(r1[0]);
                a[mt][2] = __float_as_uint(r0[4]);
                a[mt][3] = __float_as_uint(r1[4]);
            }
#pragma unroll
            for (int nt = 0; nt < 4; nt++) {
                const float* rb = &Ws[buf][wn + 8 * nt + g][kk + tig];
                b[nt][0] = __float_as_uint(rb[0]);
                b[nt][1] = __float_as_uint(rb[4]);
            }
#pragma unroll
            for (int mt = 0; mt < 4; mt++)
#pragma unroll
                for (int nt = 0; nt < 4; nt++)
                    mma_tf32(acc[mt][nt], a[mt], b[nt]);
        }
        __syncthreads();
    }

    // epilogue: c0,c1 -> row g, cols 2tig,2tig+1 ; c2,c3 -> row g+8
#pragma unroll
    for (int mt = 0; mt < 4; mt++) {
#pragma unroll
        for (int nt = 0; nt < 4; nt++) {
            int r0 = m0 + wm + 16 * mt + g;
            int cc = n0 + wn + 8 * nt + 2 * tig;
            float bs0 = bias ? bias[cc]     : 0.f;
            float bs1 = bias ? bias[cc + 1] : 0.f;
            float v0 = acc[mt][nt][0] + bs0;
            float v1 = acc[mt][nt][1] + bs1;
            float v2 = acc[mt][nt][2] + bs0;
            float v3 = acc[mt][nt][3] + bs1;
            if (EPI == 1) { v0 = mishf(v0); v1 = mishf(v1); v2 = mishf(v2); v3 = mishf(v3); }
            C[(size_t)r0 * N + cc]           = v0;
            C[(size_t)r0 * N + cc + 1]       = v1;
            C[(size_t)(r0 + 8) * N + cc]     = v2;
            C[(size_t)(r0 + 8) * N + cc + 1] = v3;
        }
    }
}

// ---------------- generic NT SGEMM (exact fp32, for qkv + skip) -------------
// EPI: 0 = C = acc + bias ; 2 = C = phi(acc) ; 3 = C += acc + bias
template <int EPI>
__global__ __launch_bounds__(256)
void sgemm_nt(const float* __restrict__ A, const float* __restrict__ B,
              const float* __restrict__ bias, float* __restrict__ C,
              int M, int N, int Kd)
{
    __shared__ float As[8][128];
    __shared__ float Bs[8][128];

    const int tid = threadIdx.x;
    const int m0  = blockIdx.y * 128;
    const int n0  = blockIdx.x * 128;
    const int tx  = tid & 15;
    const int ty  = tid >> 4;

    float acc[8][8];
#pragma unroll
    for (int i = 0; i < 8; i++)
#pragma unroll
        for (int j = 0; j < 8; j++) acc[i][j] = 0.f;

    const int lr = tid >> 1;
    const int lc = (tid & 1) * 4;

    for (int k0 = 0; k0 < Kd; k0 += 8) {
        float4 av = *(const float4*)(A + (size_t)(m0 + lr) * Kd + k0 + lc);
        float4 bv4;
        if (n0 + lr < N)
            bv4 = *(const float4*)(B + (size_t)(n0 + lr) * Kd + k0 + lc);
        else
            bv4 = make_float4(0.f, 0.f, 0.f, 0.f);

        As[lc + 0][lr] = av.x;  As[lc + 1][lr] = av.y;
        As[lc + 2][lr] = av.z;  As[lc + 3][lr] = av.w;
        Bs[lc + 0][lr] = bv4.x; Bs[lc + 1][lr] = bv4.y;
        Bs[lc + 2][lr] = bv4.z; Bs[lc + 3][lr] = bv4.w;
        __syncthreads();

#pragma unroll
        for (int kk = 0; kk < 8; kk++) {
            float4 a0 = *(const float4*)&As[kk][ty * 8];
            float4 a1 = *(const float4*)&As[kk][ty * 8 + 4];
            float4 b0 = *(const float4*)&Bs[kk][tx * 8];
            float4 b1 = *(const float4*)&Bs[kk][tx * 8 + 4];
            float a[8] = {a0.x, a0.y, a0.z, a0.w, a1.x, a1.y, a1.z, a1.w};
            float b[8] = {b0.x, b0.y, b0.z, b0.w, b1.x, b1.y, b1.z, b1.w};
#pragma unroll
            for (int i = 0; i < 8; i++)
#pragma unroll
                for (int j = 0; j < 8; j++)
                    acc[i][j] = fmaf(a[i], b[j], acc[i][j]);
        }
        __syncthreads();
    }

#pragma unroll
    for (int j = 0; j < 8; j++) {
        int n = n0 + tx * 8 + j;
        if (n >= N) continue;
        float bs = bias ? bias[n] : 0.f;
#pragma unroll
        for (int i = 0; i < 8; i++) {
            int m = m0 + ty * 8 + i;
            float v = acc[i][j] + bs;
            float* cp = C + (size_t)m * N + n;
            if (EPI == 0)      *cp = v;
            else if (EPI == 2) *cp = (v > 0.f) ? (1.f + v) : expf(v);
            else               *cp += v;  // EPI == 3
        }
    }
}

// ---------------- segmented scan (start as int32) ---------------------------
__global__ __launch_bounds__(64)
void scan_kernel(const float* __restrict__ k, const float* __restrict__ v,
                 const int* __restrict__ start,
                 const float* __restrict__ s0, const float* __restrict__ z0,
                 float* __restrict__ out_s, float* __restrict__ out_z)
{
    __shared__ float vbuf[64 * 64];
    __shared__ float kbuf[64];
    __shared__ int   sbuf[64];

    const int i = blockIdx.x;
    const int j = threadIdx.x;

    float run  = s0[i * 64 + j];
    float zrun = z0[i];

    for (int t0 = 0; t0 < Tn; t0 += 64) {
#pragma unroll 4
        for (int tt = 0; tt < 64; tt++)
            vbuf[tt * 64 + j] = v[(size_t)(t0 + tt) * 64 + j];
        kbuf[j] = k[(size_t)(t0 + j) * 64 + i];
        sbuf[j] = start[t0 + j];
        __syncthreads();

        for (int tt = 0; tt < 64; tt++) {
            if (sbuf[tt]) { run = 0.f; zrun = 0.f; }
            float kt = kbuf[tt];
            run  = fmaf(kt, vbuf[tt * 64 + j], run);
            zrun += kt;
            out_s[(size_t)(t0 + tt) * 4096 + i * 64 + j] = run;
            if (j == 0) out_z[(size_t)(t0 + tt) * 64 + i] = zrun;
        }
        __syncthreads();
    }
}

// ---------------- attention output ------------------------------------------
__global__ __launch_bounds__(64)
void attn_kernel(const float* __restrict__ s, const float* __restrict__ z,
                 const float* __restrict__ q, float* __restrict__ outp)
{
    __shared__ float qs[64];
    __shared__ float zs[64];
    __shared__ float dsh;

    const int t = blockIdx.x, j = threadIdx.x;
    qs[j] = q[t * 64 + j];
    zs[j] = z[t * 64 + j];
    __syncthreads();
    if (j == 0) {
        float qsum = 0.f, zsum = 0.f;
        for (int i = 0; i < 64; i++) { qsum += qs[i]; zsum += zs[i]; }
        dsh = fmaxf(zsum * qsum, 1e-6f);
    }
    __syncthreads();

    float acc = 0.f;
    const float* sp = s + (size_t)t * 4096;
#pragma unroll 8
    for (int i = 0; i < 64; i++)
        acc = fmaf(sp[i * 64 + j], qs[i], acc);
    outp[t * 64 + j] = acc / dsh;
}

// ---------------- LayerNorm over H ------------------------------------------
__global__ __launch_bounds__(256)
void ln_kernel(const float* __restrict__ h, const float* __restrict__ g,
               const float* __restrict__ b, float* __restrict__ o)
{
    __shared__ float red[256];
    const int t = blockIdx.x, tid = threadIdx.x;
    const float* hp = h + (size_t)t * Hn;

    float loc[16];
    float sum = 0.f;
#pragma unroll
    for (int u = 0; u < 16; u++) { loc[u] = hp[tid + u * 256]; sum += loc[u]; }
    red[tid] = sum; __syncthreads();
    for (int s = 128; s > 0; s >>= 1) { if (tid < s) red[tid] += red[tid + s]; __syncthreads(); }
    float mu = red[0] * (1.f / Hn);
    __syncthreads();

    float sq = 0.f;
#pragma unroll
    for (int u = 0; u < 16; u++) { float d = loc[u] - mu; sq += d * d; }
    red[tid] = sq; __syncthreads();
    for (int s = 128; s > 0; s >>= 1) { if (tid < s) red[tid] += red[tid + s]; __syncthreads(); }
    float inv = rsqrtf(red[0] * (1.f / Hn) + 1e-5f);

#pragma unroll
    for (int u = 0; u < 16; u++) {
        int idx = tid + u * 256;
        o[(size_t)t * Hn + idx] = (loc[u] - mu) * inv * g[idx] + b[idx];
    }
}

// ---------------- launch ----------------------------------------------------
extern "C" void kernel_launch(void* const* d_in, const int* in_sizes, int n_in,
                              void* d_out, int out_size)
{
    const float* x     = (const float*)d_in[0];
    const float* s0    = (const float*)d_in[1];
    const float* z0    = (const float*)d_in[2];
    const int*   start = (const int*)d_in[3];   // bool materialized as int32
    const float* Wk    = (const float*)d_in[5];
    const float* Wq    = (const float*)d_in[6];
    const float* Wv    = (const float*)d_in[7];
    const float* bv    = (const float*)d_in[8];
    const float* Wskip = (const float*)d_in[9];
    const float* bskip = (const float*)d_in[10];
    const float* W1    = (const float*)d_in[11];
    const float* b1    = (const float*)d_in[12];
    const float* W2    = (const float*)d_in[13];
    const float* b2    = (const float*)d_in[14];
    const float* W3    = (const float*)d_in[15];
    const float* b3    = (const float*)d_in[16];
    const float* ln_g  = (const float*)d_in[17];
    const float* ln_b  = (const float*)d_in[18];

    float* out    = (float*)d_out;
    float* out_hn = out;                               // T*H
    float* out_s  = out + (size_t)Tn * Hn;             // T*K*V
    float* out_z  = out_s + (size_t)Tn * Kn * Vn;      // T*K

    float *gk, *gq, *gv, *gatt, *gh1, *gh2;
    cudaGetSymbolAddress((void**)&gk,  g_k);
    cudaGetSymbolAddress((void**)&gq,  g_q);
    cudaGetSymbolAddress((void**)&gv,  g_v);
    cudaGetSymbolAddress((void**)&gatt, g_att);
    cudaGetSymbolAddress((void**)&gh1, g_h1);
    cudaGetSymbolAddress((void**)&gh2, g_h2);

    dim3 blk(256);
    auto grd = [](int M, int N) { return dim3((N + 127) / 128, (M + 127) / 128); };

    // qkv projections (exact fp32 — feed s,z outputs)
    sgemm_nt<2><<<grd(Tn, Kn), blk>>>(x, Wk, nullptr, gk, Tn, Kn, INn);   // k = phi
    sgemm_nt<2><<<grd(Tn, Kn), blk>>>(x, Wq, nullptr, gq, Tn, Kn, INn);   // q = phi
    sgemm_nt<0><<<grd(Tn, Vn), blk>>>(x, Wv, bv, gv, Tn, Vn, INn);        // v + bv

    // segmented scan -> writes s, z directly into d_out regions
    scan_kernel<<<64, 64>>>(gk, gv, start, s0, z0, out_s, out_z);

    // attention readout
    attn_kernel<<<Tn, 64>>>(out_s, out_z, gq, gatt);

    // MLP on tensor cores (TF32 — error lands at ~1.6e-7 of hn)
    gemm_tf32<1><<<grd(Tn, Hn), blk>>>(gatt, W1, b1, gh1, Tn, Hn, Vn);    // mish
    gemm_tf32<1><<<grd(Tn, Hn), blk>>>(gh1, W2, b2, gh2, Tn, Hn, Hn);     // mish
    gemm_tf32<0><<<grd(Tn, Hn), blk>>>(gh2, W3, b3, gh1, Tn, Hn, Hn);     // h3

    // skip connection (exact fp32 — O(1) of hn)
    sgemm_nt<3><<<grd(Tn, Hn), blk>>>(x, Wskip, bskip, gh1, Tn, Hn, INn); // += skip

    // LayerNorm -> hn
    ln_kernel<<<Tn, 256>>>(gh1, ln_g, ln_b, out_hn);
}

// round 11
// speedup vs baseline: 3.3772x; 1.7120x over previous
#include <cuda_runtime.h>
#include <cuda_bf16.h>
#include <cstdint>
#include <math.h>

#define Tn  4096
#define INn 512
#define Kn  64
#define Vn  64
#define Hn  4096
#define CH  64
#define NCH (Tn / CH)

// ---------------- scratch (device globals; no cudaMalloc allowed) -----------
__device__ float g_k  [Tn * Kn];
__device__ float g_q  [Tn * Kn];
__device__ float g_v  [Tn * Vn];
__device__ float g_h3 [Tn * Hn];               // fp32: h3 + skip accumulator
__device__ __nv_bfloat16 g_attb[Tn * Vn];      // att in bf16 (feeds W1)
__device__ __nv_bfloat16 g_h1b [Tn * Hn];
__device__ __nv_bfloat16 g_h2b [Tn * Hn];
__device__ __nv_bfloat16 g_w1b [Hn * Vn];
__device__ __nv_bfloat16 g_w2b [(size_t)Hn * Hn];
__device__ __nv_bfloat16 g_w3b [(size_t)Hn * Hn];
__device__ __nv_bfloat16 g_xh  [Tn * INn];
__device__ __nv_bfloat16 g_xl  [Tn * INn];
__device__ __nv_bfloat16 g_wsh [Hn * INn];
__device__ __nv_bfloat16 g_wsl [Hn * INn];
// scan scratch
__device__ float g_L  [NCH * Kn * Vn];
__device__ float g_Sin[NCH * Kn * Vn];
__device__ float g_Lz [NCH * Kn];
__device__ float g_Zin[NCH * Kn];
__device__ int   g_keep[NCH];

// ---------------- activations ----------------------------------------------
__device__ __forceinline__ float mishf(float x) {
    if (x > 20.f) return x;
    float u = expf(x);
    float w = u * (u + 2.f);
    return x * w / (w + 2.f);
}

// ---------------- fp32 -> bf16 conversions -----------------------------------
__global__ void f2bf(const float* __restrict__ in, __nv_bfloat16* __restrict__ out, int n) {
    int i = blockIdx.x * 256 + threadIdx.x;
    if (i < n) out[i] = __float2bfloat16(in[i]);
}
// split: hi = bf16(v), lo = bf16(v - hi)  (3-product split-bf16 GEMM operands)
__global__ void f2bf_split(const float* __restrict__ in,
                           __nv_bfloat16* __restrict__ hi, __nv_bfloat16* __restrict__ lo, int n) {
    int i = blockIdx.x * 256 + threadIdx.x;
    if (i < n) {
        float v = in[i];
        __nv_bfloat16 h = __float2bfloat16(v);
        hi[i] = h;
        lo[i] = __float2bfloat16(v - __bfloat162float(h));
    }
}

// ======================= bf16 tensor-core GEMM ================================
// C[M,N] = A[M,K] * W[N,K]^T (+bias). m16n8k16 bf16 mma, fp32 accumulate.
// 128x128 tile, K-chunk 32, cp.async double buffer, 8 warps of 64x32.
// smem [row][k] bf16 with row stride 40 (=20 words): fragment word addrs
// 20g + tig(+4) hit disjoint bank quads -> conflict-free.
#define BKB 32

__device__ __forceinline__ void cp_async16(uint32_t saddr, const void* gaddr) {
    asm volatile("cp.async.cg.shared.global [%0], [%1], 16;\n" :: "r"(saddr), "l"(gaddr));
}
__device__ __forceinline__ void cp_commit() { asm volatile("cp.async.commit_group;\n"); }
template <int N>
__device__ __forceinline__ void cp_wait() { asm volatile("cp.async.wait_group %0;\n" :: "n"(N)); }

__device__ __forceinline__ void mma_bf16(float* d, const uint32_t* a, const uint32_t* b) {
    asm volatile(
        "mma.sync.aligned.m16n8k16.row.col.f32.bf16.bf16.f32 "
        "{%0,%1,%2,%3}, {%4,%5,%6,%7}, {%8,%9}, {%0,%1,%2,%3};\n"
        : "+f"(d[0]), "+f"(d[1]), "+f"(d[2]), "+f"(d[3])
        : "r"(a[0]), "r"(a[1]), "r"(a[2]), "r"(a[3]), "r"(b[0]), "r"(b[1]));
}

// EPI: 0 = fp32 store (acc+bias) ; 1 = mish(acc+bias) -> bf16 store
//      2 = fp32 accumulate (C += acc + bias)
template <int EPI>
__global__ __launch_bounds__(256)
void gemm_bf16(const __nv_bfloat16* __restrict__ A, const __nv_bfloat16* __restrict__ W,
               const float* __restrict__ bias, void* __restrict__ Cv,
               int M, int N, int K)
{
    __shared__ __nv_bfloat16 As[2][128][40];
    __shared__ __nv_bfloat16 Ws[2][128][40];

    const int tid  = threadIdx.x;
    const int lane = tid & 31;
    const int wid  = tid >> 5;
    const int g    = lane >> 2;
    const int tig  = lane & 3;
    const int wm   = (wid & 1) * 64;
    const int wn   = (wid >> 1) * 32;
    const int m0   = blockIdx.y * 128;
    const int n0   = blockIdx.x * 128;

    const int ld_row = tid & 127;
    const bool is_a  = tid < 128;
    const __nv_bfloat16* gbase = is_a ? (A + (size_t)(m0 + ld_row) * K)
                                      : (W + (size_t)(n0 + ld_row) * K);

    float acc[4][4][4];
#pragma unroll
    for (int mt = 0; mt < 4; mt++)
#pragma unroll
        for (int nt = 0; nt < 4; nt++)
#pragma unroll
            for (int r = 0; r < 4; r++) acc[mt][nt][r] = 0.f;

    auto issue = [&](int it) {
        int buf = it & 1;
        __nv_bfloat16* srow = is_a ? &As[buf][ld_row][0] : &Ws[buf][ld_row][0];
        uint32_t sa = (uint32_t)__cvta_generic_to_shared(srow);
        const __nv_bfloat16* gp = gbase + it * BKB;
#pragma unroll
        for (int ch = 0; ch < 4; ch++)
            cp_async16(sa + ch * 16, gp + ch * 8);   // 8 bf16 = 16B
        cp_commit();
    };

    const int niter = K / BKB;
    issue(0);

    for (int it = 0; it < niter; it++) {
        if (it + 1 < niter) { issue(it + 1); cp_wait<1>(); }
        else                {               cp_wait<0>(); }
        __syncthreads();

        const int buf = it & 1;
#pragma unroll
        for (int kk = 0; kk < BKB; kk += 16) {
            uint32_t a[4][4], b[4][2];
#pragma unroll
            for (int mt = 0; mt < 4; mt++) {
                const __nv_bfloat16* r0 = &As[buf][wm + 16 * mt + g][kk + 2 * tig];
                const __nv_bfloat16* r1 = &As[buf][wm + 16 * mt + 8 + g][kk + 2 * tig];
                a[mt][0] = *(const uint32_t*)r0;
                a[mt][1] = *(const uint32_t*)r1;
                a[mt][2] = *(const uint32_t*)(r0 + 8);
                a[mt][3] = *(const uint32_t*)(r1 + 8);
            }
#pragma unroll
            for (int nt = 0; nt < 4; nt++) {
                const __nv_bfloat16* rb = &Ws[buf][wn + 8 * nt + g][kk + 2 * tig];
                b[nt][0] = *(const uint32_t*)rb;
                b[nt][1] = *(const uint32_t*)(rb + 8);
            }
#pragma unroll
            for (int mt = 0; mt < 4; mt++)
#pragma unroll
                for (int nt = 0; nt < 4; nt++)
                    mma_bf16(acc[mt][nt], a[mt], b[nt]);
        }
        __syncthreads();
    }

#pragma unroll
    for (int mt = 0; mt < 4; mt++) {
#pragma unroll
        for (int nt = 0; nt < 4; nt++) {
            int r0 = m0 + wm + 16 * mt + g;
            int cc = n0 + wn + 8 * nt + 2 * tig;
            float bs0 = bias ? bias[cc]     : 0.f;
            float bs1 = bias ? bias[cc + 1] : 0.f;
            float v0 = acc[mt][nt][0] + bs0;
            float v1 = acc[mt][nt][1] + bs1;
            float v2 = acc[mt][nt][2] + bs0;
            float v3 = acc[mt][nt][3] + bs1;
            if (EPI == 1) {
                __nv_bfloat16* C = (__nv_bfloat16*)Cv;
                C[(size_t)r0 * N + cc]           = __float2bfloat16(mishf(v0));
                C[(size_t)r0 * N + cc + 1]       = __float2bfloat16(mishf(v1));
                C[(size_t)(r0 + 8) * N + cc]     = __float2bfloat16(mishf(v2));
                C[(size_t)(r0 + 8) * N + cc + 1] = __float2bfloat16(mishf(v3));
            } else if (EPI == 0) {
                float* C = (float*)Cv;
                C[(size_t)r0 * N + cc]           = v0;
                C[(size_t)r0 * N + cc + 1]       = v1;
                C[(size_t)(r0 + 8) * N + cc]     = v2;
                C[(size_t)(r0 + 8) * N + cc + 1] = v3;
            } else {
                float* C = (float*)Cv;
                C[(size_t)r0 * N + cc]           += v0;
                C[(size_t)r0 * N + cc + 1]       += v1;
                C[(size_t)(r0 + 8) * N + cc]     += v2;
                C[(size_t)(r0 + 8) * N + cc + 1] += v3;
            }
        }
    }
}

// ---------------- generic NT SGEMM (exact fp32, for qkv) ---------------------
// EPI: 0 = C = acc + bias ; 2 = C = phi(acc)
template <int EPI>
__global__ __launch_bounds__(256)
void sgemm_nt(const float* __restrict__ A, const float* __restrict__ B,
              const float* __restrict__ bias, float* __restrict__ C,
              int M, int N, int Kd)
{
    __shared__ float As[8][128];
    __shared__ float Bs[8][128];

    const int tid = threadIdx.x;
    const int m0  = blockIdx.y * 128;
    const int n0  = blockIdx.x * 128;
    const int tx  = tid & 15;
    const int ty  = tid >> 4;

    float acc[8][8];
#pragma unroll
    for (int i = 0; i < 8; i++)
#pragma unroll
        for (int j = 0; j < 8; j++) acc[i][j] = 0.f;

    const int lr = tid >> 1;
    const int lc = (tid & 1) * 4;

    for (int k0 = 0; k0 < Kd; k0 += 8) {
        float4 av = *(const float4*)(A + (size_t)(m0 + lr) * Kd + k0 + lc);
        float4 bv4;
        if (n0 + lr < N)
            bv4 = *(const float4*)(B + (size_t)(n0 + lr) * Kd + k0 + lc);
        else
            bv4 = make_float4(0.f, 0.f, 0.f, 0.f);

        As[lc + 0][lr] = av.x;  As[lc + 1][lr] = av.y;
        As[lc + 2][lr] = av.z;  As[lc + 3][lr] = av.w;
        Bs[lc + 0][lr] = bv4.x; Bs[lc + 1][lr] = bv4.y;
        Bs[lc + 2][lr] = bv4.z; Bs[lc + 3][lr] = bv4.w;
        __syncthreads();

#pragma unroll
        for (int kk = 0; kk < 8; kk++) {
            float4 a0 = *(const float4*)&As[kk][ty * 8];
            float4 a1 = *(const float4*)&As[kk][ty * 8 + 4];
            float4 b0 = *(const float4*)&Bs[kk][tx * 8];
            float4 b1 = *(const float4*)&Bs[kk][tx * 8 + 4];
            float a[8] = {a0.x, a0.y, a0.z, a0.w, a1.x, a1.y, a1.z, a1.w};
            float b[8] = {b0.x, b0.y, b0.z, b0.w, b1.x, b1.y, b1.z, b1.w};
#pragma unroll
            for (int i = 0; i < 8; i++)
#pragma unroll
                for (int j = 0; j < 8; j++)
                    acc[i][j] = fmaf(a[i], b[j], acc[i][j]);
        }
        __syncthreads();
    }

#pragma unroll
    for (int j = 0; j < 8; j++) {
        int n = n0 + tx * 8 + j;
        if (n >= N) continue;
        float bs = bias ? bias[n] : 0.f;
#pragma unroll
        for (int i = 0; i < 8; i++) {
            int m = m0 + ty * 8 + i;
            float v = acc[i][j] + bs;
            float* cp = C + (size_t)m * N + n;
            if (EPI == 0) *cp = v;
            else          *cp = (v > 0.f) ? (1.f + v) : expf(v);
        }
    }
}

// ---------------- chunked segmented scan --------------------------------------
// run[t] = (start[t] ? 0 : run[t-1]) + k_t (x) v_t ; same for z with k only.
// Pass A: per-chunk local carries (from zero).  Pass B: serial combine of NCH
// carries (1 block).  Pass C: emit outputs given incoming state per chunk.
__global__ __launch_bounds__(64)
void scan_carry(const float* __restrict__ k, const float* __restrict__ v,
                const int* __restrict__ start,
                float* __restrict__ L, float* __restrict__ Lz, int* __restrict__ keepf)
{
    __shared__ float kbuf[CH];
    __shared__ int   sbuf[CH];
    const int c = blockIdx.x, i = blockIdx.y, j = threadIdx.x;
    const int t0 = c * CH;
    kbuf[j] = k[(size_t)(t0 + j) * Kn + i];
    sbuf[j] = start[t0 + j];
    __syncthreads();

    float run = 0.f, zr = 0.f;
    int anyst = 0;
    for (int tt = 0; tt < CH; tt++) {
        if (sbuf[tt]) { run = 0.f; zr = 0.f; anyst = 1; }
        float kt = kbuf[tt];
        run = fmaf(kt, v[(size_t)(t0 + tt) * Vn + j], run);
        zr += kt;
    }
    L[c * (Kn * Vn) + i * Vn + j] = run;
    if (j == 0) Lz[c * Kn + i] = zr;
    if (i == 0 && j == 0) keepf[c] = !anyst;
}

__global__ __launch_bounds__(1024)
void scan_combine(const float* __restrict__ s0, const float* __restrict__ z0,
                  const float* __restrict__ L, const float* __restrict__ Lz,
                  const int* __restrict__ keepf,
                  float* __restrict__ Sin, float* __restrict__ Zin)
{
    const int tid = threadIdx.x;      // 1024 threads, 4 s-entries each
    float S[4];
#pragma unroll
    for (int u = 0; u < 4; u++) S[u] = s0[tid * 4 + u];
    float Z = (tid < Kn) ? z0[tid] : 0.f;

    for (int c = 0; c < NCH; c++) {
#pragma unroll
        for (int u = 0; u < 4; u++) Sin[c * (Kn * Vn) + tid * 4 + u] = S[u];
        if (tid < Kn) Zin[c * Kn + tid] = Z;
        int kp = keepf[c];
#pragma unroll
        for (int u = 0; u < 4; u++)
            S[u] = (kp ? S[u] : 0.f) + L[c * (Kn * Vn) + tid * 4 + u];
        if (tid < Kn) Z = (kp ? Z : 0.f) + Lz[c * Kn + tid];
    }
}

__global__ __launch_bounds__(64)
void scan_out(const float* __restrict__ k, const float* __restrict__ v,
              const int* __restrict__ start,
              const float* __restrict__ Sin, const float* __restrict__ Zin,
              float* __restrict__ out_s, float* __restrict__ out_z)
{
    __shared__ float kbuf[CH];
    __shared__ int   sbuf[CH];
    const int c = blockIdx.x, i = blockIdx.y, j = threadIdx.x;
    const int t0 = c * CH;
    kbuf[j] = k[(size_t)(t0 + j) * Kn + i];
    sbuf[j] = start[t0 + j];
    __syncthreads();

    float run = Sin[c * (Kn * Vn) + i * Vn + j];
    float zr  = Zin[c * Kn + i];
    for (int tt = 0; tt < CH; tt++) {
        if (sbuf[tt]) { run = 0.f; zr = 0.f; }
        float kt = kbuf[tt];
        run = fmaf(kt, v[(size_t)(t0 + tt) * Vn + j], run);
        zr += kt;
        out_s[(size_t)(t0 + tt) * (Kn * Vn) + i * Vn + j] = run;
        if (j == 0) out_z[(size_t)(t0 + tt) * Kn + i] = zr;
    }
}

// ---------------- attention output (writes bf16 att) -------------------------
__global__ __launch_bounds__(64)
void attn_kernel(const float* __restrict__ s, const float* __restrict__ z,
                 const float* __restrict__ q, __nv_bfloat16* __restrict__ outp)
{
    __shared__ float qs[64];
    __shared__ float zs[64];
    __shared__ float dsh;

    const int t = blockIdx.x, j = threadIdx.x;
    qs[j] = q[t * 64 + j];
    zs[j] = z[t * 64 + j];
    __syncthreads();
    if (j == 0) {
        float qsum = 0.f, zsum = 0.f;
        for (int i = 0; i < 64; i++) { qsum += qs[i]; zsum += zs[i]; }
        dsh = fmaxf(zsum * qsum, 1e-6f);
    }
    __syncthreads();

    float acc = 0.f;
    const float* sp = s + (size_t)t * 4096;
#pragma unroll 8
    for (int i = 0; i < 64; i++)
        acc = fmaf(sp[i * 64 + j], qs[i], acc);
    outp[t * 64 + j] = __float2bfloat16(acc / dsh);
}

// ---------------- LayerNorm over H ------------------------------------------
__global__ __launch_bounds__(256)
void ln_kernel(const float* __restrict__ h, const float* __restrict__ g,
               const float* __restrict__ b, float* __restrict__ o)
{
    __shared__ float red[256];
    const int t = blockIdx.x, tid = threadIdx.x;
    const float* hp = h + (size_t)t * Hn;

    float loc[16];
    float sum = 0.f;
#pragma unroll
    for (int u = 0; u < 16; u++) { loc[u] = hp[tid + u * 256]; sum += loc[u]; }
    red[tid] = sum; __syncthreads();
    for (int s = 128; s > 0; s >>= 1) { if (tid < s) red[tid] += red[tid + s]; __syncthreads(); }
    float mu = red[0] * (1.f / Hn);
    __syncthreads();

    float sq = 0.f;
#pragma unroll
    for (int u = 0; u < 16; u++) { float d = loc[u] - mu; sq += d * d; }
    red[tid] = sq; __syncthreads();
    for (int s = 128; s > 0; s >>= 1) { if (tid < s) red[tid] += red[tid + s]; __syncthreads(); }
    float inv = rsqrtf(red[0] * (1.f / Hn) + 1e-5f);

#pragma unroll
    for (int u = 0; u < 16; u++) {
        int idx = tid + u * 256;
        o[(size_t)t * Hn + idx] = (loc[u] - mu) * inv * g[idx] + b[idx];
    }
}

// ---------------- launch ----------------------------------------------------
extern "C" void kernel_launch(void* const* d_in, const int* in_sizes, int n_in,
                              void* d_out, int out_size)
{
    const float* x     = (const float*)d_in[0];
    const float* s0    = (const float*)d_in[1];
    const float* z0    = (const float*)d_in[2];
    const int*   start = (const int*)d_in[3];   // bool materialized as int32
    const float* Wk    = (const float*)d_in[5];
    const float* Wq    = (const float*)d_in[6];
    const float* Wv    = (const float*)d_in[7];
    const float* bv    = (const float*)d_in[8];
    const float* Wskip = (const float*)d_in[9];
    const float* bskip = (const float*)d_in[10];
    const float* W1    = (const float*)d_in[11];
    const float* b1    = (const float*)d_in[12];
    const float* W2    = (const float*)d_in[13];
    const float* b2    = (const float*)d_in[14];
    const float* W3    = (const float*)d_in[15];
    const float* b3    = (const float*)d_in[16];
    const float* ln_g  = (const float*)d_in[17];
    const float* ln_b  = (const float*)d_in[18];

    float* out    = (float*)d_out;
    float* out_hn = out;
    float* out_s  = out + (size_t)Tn * Hn;
    float* out_z  = out_s + (size_t)Tn * Kn * Vn;

    float *gk, *gq, *gv, *gh3, *gL, *gSin, *gLz, *gZin;
    int* gkeep;
    __nv_bfloat16 *gattb, *gh1b, *gh2b, *gw1b, *gw2b, *gw3b, *gxh, *gxl, *gwsh, *gwsl;
    cudaGetSymbolAddress((void**)&gk,   g_k);
    cudaGetSymbolAddress((void**)&gq,   g_q);
    cudaGetSymbolAddress((void**)&gv,   g_v);
    cudaGetSymbolAddress((void**)&gh3,  g_h3);
    cudaGetSymbolAddress((void**)&gattb, g_attb);
    cudaGetSymbolAddress((void**)&gh1b, g_h1b);
    cudaGetSymbolAddress((void**)&gh2b, g_h2b);
    cudaGetSymbolAddress((void**)&gw1b, g_w1b);
    cudaGetSymbolAddress((void**)&gw2b, g_w2b);
    cudaGetSymbolAddress((void**)&gw3b, g_w3b);
    cudaGetSymbolAddress((void**)&gxh,  g_xh);
    cudaGetSymbolAddress((void**)&gxl,  g_xl);
    cudaGetSymbolAddress((void**)&gwsh, g_wsh);
    cudaGetSymbolAddress((void**)&gwsl, g_wsl);
    cudaGetSymbolAddress((void**)&gL,   g_L);
    cudaGetSymbolAddress((void**)&gSin, g_Sin);
    cudaGetSymbolAddress((void**)&gLz,  g_Lz);
    cudaGetSymbolAddress((void**)&gZin, g_Zin);
    cudaGetSymbolAddress((void**)&gkeep, g_keep);

    dim3 blk(256);
    auto grd = [](int M, int N) { return dim3((N + 127) / 128, (M + 127) / 128); };
    auto cgrd = [](int n) { return dim3((n + 255) / 256); };

    // weight/operand conversions (deterministic each launch)
    f2bf<<<cgrd(Hn * Vn), blk>>>(W1, gw1b, Hn * Vn);
    f2bf<<<cgrd(Hn * Hn), blk>>>(W2, gw2b, Hn * Hn);
    f2bf<<<cgrd(Hn * Hn), blk>>>(W3, gw3b, Hn * Hn);
    f2bf_split<<<cgrd(Tn * INn), blk>>>(x, gxh, gxl, Tn * INn);
    f2bf_split<<<cgrd(Hn * INn), blk>>>(Wskip, gwsh, gwsl, Hn * INn);

    // qkv projections (exact fp32 — feed s,z outputs)
    sgemm_nt<2><<<grd(Tn, Kn), blk>>>(x, Wk, nullptr, gk, Tn, Kn, INn);
    sgemm_nt<2><<<grd(Tn, Kn), blk>>>(x, Wq, nullptr, gq, Tn, Kn, INn);
    sgemm_nt<0><<<grd(Tn, Vn), blk>>>(x, Wv, bv, gv, Tn, Vn, INn);

    // chunked segmented scan -> s,z into d_out
    scan_carry<<<dim3(NCH, Kn), 64>>>(gk, gv, start, gL, gLz, gkeep);
    scan_combine<<<1, 1024>>>(s0, z0, gL, gLz, gkeep, gSin, gZin);
    scan_out<<<dim3(NCH, Kn), 64>>>(gk, gv, start, gSin, gZin, out_s, out_z);

    // attention readout -> bf16 att
    attn_kernel<<<Tn, 64>>>(out_s, out_z, gq, gattb);

    // MLP on bf16 tensor cores (branch is ~4e-4 of hn -> bf16 noise ~6e-7 at hn)
    gemm_bf16<1><<<grd(Tn, Hn), blk>>>(gattb, gw1b, b1, gh1b, Tn, Hn, Vn);
    gemm_bf16<1><<<grd(Tn, Hn), blk>>>(gh1b, gw2b, b2, gh2b, Tn, Hn, Hn);
    gemm_bf16<0><<<grd(Tn, Hn), blk>>>(gh2b, gw3b, b3, gh3, Tn, Hn, Hn);

    // skip: split-bf16 3-product (error ~4e-6, exact enough for O(1) branch)
    gemm_bf16<2><<<grd(Tn, Hn), blk>>>(gxh, gwsh, bskip, gh3, Tn, Hn, INn);
    gemm_bf16<2><<<grd(Tn, Hn), blk>>>(gxh, gwsl, nullptr, gh3, Tn, Hn, INn);
    gemm_bf16<2><<<grd(Tn, Hn), blk>>>(gxl, gwsh, nullptr, gh3, Tn, Hn, INn);

    // LayerNorm -> hn
    ln_kernel<<<Tn, 256>>>(gh3, ln_g, ln_b, out_hn);
}

// round 12
// speedup vs baseline: 3.9337x; 1.1648x over previous
#include <cuda_runtime.h>
#include <cuda_bf16.h>
#include <cstdint>
#include <math.h>

#define Tn  4096
#define INn 512
#define Kn  64
#define Vn  64
#define Hn  4096
#define CH  64
#define NCH (Tn / CH)

// ---------------- scratch (device globals; no cudaMalloc allowed) -----------
__device__ float g_k  [Tn * Kn];
__device__ float g_q  [Tn * Kn];
__device__ float g_v  [Tn * Vn];
__device__ float g_h3 [Tn * Hn];               // fp32: h3 + skip accumulator
__device__ float g_wqkv[192 * INn];            // concat Wk|Wq|Wv
__device__ __nv_bfloat16 g_attb[Tn * Vn];
__device__ __nv_bfloat16 g_h1b [Tn * Hn];
__device__ __nv_bfloat16 g_h2b [Tn * Hn];
__device__ __nv_bfloat16 g_w1b [Hn * Vn];
__device__ __nv_bfloat16 g_w2b [(size_t)Hn * Hn];
__device__ __nv_bfloat16 g_w3b [(size_t)Hn * Hn];
__device__ __nv_bfloat16 g_xh  [Tn * INn];          // xh contiguous (K=512)
__device__ __nv_bfloat16 g_wsh [Hn * INn];          // Wskip hi contiguous
__device__ __nv_bfloat16 g_xcat[(size_t)Tn * 2 * INn];  // [xh | xl]
__device__ __nv_bfloat16 g_wcat[(size_t)Hn * 2 * INn];  // [Wsl | Wsh]
// scan scratch
__device__ float g_L  [NCH * Kn * Vn];
__device__ float g_Sin[NCH * Kn * Vn];
__device__ float g_Lz [NCH * Kn];
__device__ float g_Zin[NCH * Kn];
__device__ int   g_keep[NCH];

// ---------------- activations ----------------------------------------------
__device__ __forceinline__ float mishf(float x) {
    if (x > 20.f) return x;
    float u = expf(x);
    float w = u * (u + 2.f);
    return x * w / (w + 2.f);
}

// ---------------- fp32 -> bf16 conversions -----------------------------------
__global__ void f2bf(const float* __restrict__ in, __nv_bfloat16* __restrict__ out, int n) {
    int i = blockIdx.x * 256 + threadIdx.x;
    if (i < n) out[i] = __float2bfloat16(in[i]);
}
// split for x: hi -> xh (contig) and xcat[:, 0:512]; lo -> xcat[:, 512:1024]
__global__ void split_x(const float* __restrict__ in, __nv_bfloat16* __restrict__ hi,
                        __nv_bfloat16* __restrict__ cat, int n) {
    int i = blockIdx.x * 256 + threadIdx.x;
    if (i < n) {
        float v = in[i];
        __nv_bfloat16 h = __float2bfloat16(v);
        __nv_bfloat16 l = __float2bfloat16(v - __bfloat162float(h));
        int r = i / INn, c = i % INn;
        hi[i] = h;
        cat[(size_t)r * (2 * INn) + c] = h;
        cat[(size_t)r * (2 * INn) + INn + c] = l;
    }
}
// split for W: hi -> wsh (contig) and wcat[:, 512:1024]; lo -> wcat[:, 0:512]
__global__ void split_w(const float* __restrict__ in, __nv_bfloat16* __restrict__ hi,
                        __nv_bfloat16* __restrict__ cat, int n) {
    int i = blockIdx.x * 256 + threadIdx.x;
    if (i < n) {
        float v = in[i];
        __nv_bfloat16 h = __float2bfloat16(v);
        __nv_bfloat16 l = __float2bfloat16(v - __bfloat162float(h));
        int r = i / INn, c = i % INn;
        hi[i] = h;
        cat[(size_t)r * (2 * INn) + c] = l;
        cat[(size_t)r * (2 * INn) + INn + c] = h;
    }
}

// ======================= bf16 tensor-core GEMM ================================
// C[M,N] = A[M,K] * W[N,K]^T (+bias). m16n8k16 bf16 mma, fp32 accumulate.
// 128x128 tile, K-chunk 32, cp.async double buffer, 8 warps of 64x32.
// Fragments loaded via ldmatrix.x4: stride-40 bf16 rows -> the 8 row pointers
// of each 8x8 matrix hit all 32 banks exactly once (conflict-free).
#define BKB 32

__device__ __forceinline__ void cp_async16(uint32_t saddr, const void* gaddr) {
    asm volatile("cp.async.cg.shared.global [%0], [%1], 16;\n" :: "r"(saddr), "l"(gaddr));
}
__device__ __forceinline__ void cp_commit() { asm volatile("cp.async.commit_group;\n"); }
template <int N>
__device__ __forceinline__ void cp_wait() { asm volatile("cp.async.wait_group %0;\n" :: "n"(N)); }

__device__ __forceinline__ void mma_bf16(float* d, const uint32_t* a, const uint32_t* b) {
    asm volatile(
        "mma.sync.aligned.m16n8k16.row.col.f32.bf16.bf16.f32 "
        "{%0,%1,%2,%3}, {%4,%5,%6,%7}, {%8,%9}, {%0,%1,%2,%3};\n"
        : "+f"(d[0]), "+f"(d[1]), "+f"(d[2]), "+f"(d[3])
        : "r"(a[0]), "r"(a[1]), "r"(a[2]), "r"(a[3]), "r"(b[0]), "r"(b[1]));
}

// EPI: 0 = fp32 store (acc+bias) ; 1 = mish(acc+bias) -> bf16 store
//      2 = fp32 accumulate (C += acc + bias)
template <int EPI>
__global__ __launch_bounds__(256)
void gemm_bf16(const __nv_bfloat16* __restrict__ A, const __nv_bfloat16* __restrict__ W,
               const float* __restrict__ bias, void* __restrict__ Cv,
               int M, int N, int K)
{
    __shared__ __align__(16) __nv_bfloat16 As[2][128][40];
    __shared__ __align__(16) __nv_bfloat16 Ws[2][128][40];

    const int tid  = threadIdx.x;
    const int lane = tid & 31;
    const int wid  = tid >> 5;
    const int g    = lane >> 2;
    const int tig  = lane & 3;
    const int wm   = (wid & 1) * 64;
    const int wn   = (wid >> 1) * 32;
    const int m0   = blockIdx.y * 128;
    const int n0   = blockIdx.x * 128;

    const int ld_row = tid & 127;
    const bool is_a  = tid < 128;
    const __nv_bfloat16* gbase = is_a ? (A + (size_t)(m0 + ld_row) * K)
                                      : (W + (size_t)(n0 + ld_row) * K);

    float acc[4][4][4];
#pragma unroll
    for (int mt = 0; mt < 4; mt++)
#pragma unroll
        for (int nt = 0; nt < 4; nt++)
#pragma unroll
            for (int r = 0; r < 4; r++) acc[mt][nt][r] = 0.f;

    auto issue = [&](int it) {
        int buf = it & 1;
        __nv_bfloat16* srow = is_a ? &As[buf][ld_row][0] : &Ws[buf][ld_row][0];
        uint32_t sa = (uint32_t)__cvta_generic_to_shared(srow);
        const __nv_bfloat16* gp = gbase + it * BKB;
#pragma unroll
        for (int ch = 0; ch < 4; ch++)
            cp_async16(sa + ch * 16, gp + ch * 8);
        cp_commit();
    };

    const int niter = K / BKB;
    issue(0);

    // ldmatrix addressing (constant per thread)
    const int a_m  = lane & 15;            // m within 16-tile
    const int a_k  = (lane >> 4) * 8;      // k half
    const int b_g8 = lane >> 3;            // 0..3
    const int b_n  = (lane & 7) + 8 * (b_g8 >> 1);
    const int b_k  = (b_g8 & 1) * 8;

    for (int it = 0; it < niter; it++) {
        if (it + 1 < niter) { issue(it + 1); cp_wait<1>(); }
        else                {               cp_wait<0>(); }
        __syncthreads();

        const int buf = it & 1;
#pragma unroll
        for (int kk = 0; kk < BKB; kk += 16) {
            uint32_t a[4][4], b[4][2];
#pragma unroll
            for (int mt = 0; mt < 4; mt++) {
                uint32_t sa = (uint32_t)__cvta_generic_to_shared(
                    &As[buf][wm + 16 * mt + a_m][kk + a_k]);
                asm volatile("ldmatrix.sync.aligned.m8n8.x4.shared.b16 {%0,%1,%2,%3}, [%4];"
                    : "=r"(a[mt][0]), "=r"(a[mt][1]), "=r"(a[mt][2]), "=r"(a[mt][3])
                    : "r"(sa));
            }
#pragma unroll
            for (int p = 0; p < 2; p++) {
                uint32_t sb = (uint32_t)__cvta_generic_to_shared(
                    &Ws[buf][wn + 16 * p + b_n][kk + b_k]);
                asm volatile("ldmatrix.sync.aligned.m8n8.x4.shared.b16 {%0,%1,%2,%3}, [%4];"
                    : "=r"(b[2 * p][0]), "=r"(b[2 * p][1]),
                      "=r"(b[2 * p + 1][0]), "=r"(b[2 * p + 1][1])
                    : "r"(sb));
            }
#pragma unroll
            for (int mt = 0; mt < 4; mt++)
#pragma unroll
                for (int nt = 0; nt < 4; nt++)
                    mma_bf16(acc[mt][nt], a[mt], b[nt]);
        }
        __syncthreads();
    }

#pragma unroll
    for (int mt = 0; mt < 4; mt++) {
#pragma unroll
        for (int nt = 0; nt < 4; nt++) {
            int r0 = m0 + wm + 16 * mt + g;
            int cc = n0 + wn + 8 * nt + 2 * tig;
            float bs0 = bias ? bias[cc]     : 0.f;
            float bs1 = bias ? bias[cc + 1] : 0.f;
            float v0 = acc[mt][nt][0] + bs0;
            float v1 = acc[mt][nt][1] + bs1;
            float v2 = acc[mt][nt][2] + bs0;
            float v3 = acc[mt][nt][3] + bs1;
            if (EPI == 1) {
                __nv_bfloat16* C = (__nv_bfloat16*)Cv;
                C[(size_t)r0 * N + cc]           = __float2bfloat16(mishf(v0));
                C[(size_t)r0 * N + cc + 1]       = __float2bfloat16(mishf(v1));
                C[(size_t)(r0 + 8) * N + cc]     = __float2bfloat16(mishf(v2));
                C[(size_t)(r0 + 8) * N + cc + 1] = __float2bfloat16(mishf(v3));
            } else if (EPI == 0) {
                float* C = (float*)Cv;
                C[(size_t)r0 * N + cc]           = v0;
                C[(size_t)r0 * N + cc + 1]       = v1;
                C[(size_t)(r0 + 8) * N + cc]     = v2;
                C[(size_t)(r0 + 8) * N + cc + 1] = v3;
            } else {
                float* C = (float*)Cv;
                C[(size_t)r0 * N + cc]           += v0;
                C[(size_t)r0 * N + cc + 1]       += v1;
                C[(size_t)(r0 + 8) * N + cc]     += v2;
                C[(size_t)(r0 + 8) * N + cc + 1] += v3;
            }
        }
    }
}

// ---------------- fused qkv GEMM (exact fp32, 64x64 tiles, full chip) --------
// Wc = concat rows [Wk(0:64) | Wq(64:128) | Wv(128:192)], K=512.
__global__ __launch_bounds__(256)
void qkv_gemm(const float* __restrict__ x, const float* __restrict__ Wc,
              const float* __restrict__ bv,
              float* __restrict__ ko, float* __restrict__ qo, float* __restrict__ vo)
{
    __shared__ float As[16][64];
    __shared__ float Bs[16][64];
    const int tid = threadIdx.x;
    const int tx = tid & 15, ty = tid >> 4;
    const int m0 = blockIdx.y * 64, n0 = blockIdx.x * 64;
    const int lrow = tid >> 2, lk = (tid & 3) * 4;

    float acc[4][4];
#pragma unroll
    for (int i = 0; i < 4; i++)
#pragma unroll
        for (int j = 0; j < 4; j++) acc[i][j] = 0.f;

    for (int k0 = 0; k0 < INn; k0 += 16) {
        float4 av = *(const float4*)(x  + (size_t)(m0 + lrow) * INn + k0 + lk);
        float4 bw = *(const float4*)(Wc + (size_t)(n0 + lrow) * INn + k0 + lk);
        As[lk + 0][lrow] = av.x; As[lk + 1][lrow] = av.y;
        As[lk + 2][lrow] = av.z; As[lk + 3][lrow] = av.w;
        Bs[lk + 0][lrow] = bw.x; Bs[lk + 1][lrow] = bw.y;
        Bs[lk + 2][lrow] = bw.z; Bs[lk + 3][lrow] = bw.w;
        __syncthreads();
#pragma unroll
        for (int kk = 0; kk < 16; kk++) {
            float a[4], b[4];
#pragma unroll
            for (int u = 0; u < 4; u++) { a[u] = As[kk][ty * 4 + u]; b[u] = Bs[kk][tx * 4 + u]; }
#pragma unroll
            for (int i = 0; i < 4; i++)
#pragma unroll
                for (int j = 0; j < 4; j++)
                    acc[i][j] = fmaf(a[i], b[j], acc[i][j]);
        }
        __syncthreads();
    }

#pragma unroll
    for (int i = 0; i < 4; i++) {
        int m = m0 + ty * 4 + i;
#pragma unroll
        for (int j = 0; j < 4; j++) {
            int n = n0 + tx * 4 + j;
            float vv = acc[i][j];
            if (n < 64)       ko[m * 64 + n]       = (vv > 0.f) ? (1.f + vv) : expf(vv);
            else if (n < 128) qo[m * 64 + n - 64]  = (vv > 0.f) ? (1.f + vv) : expf(vv);
            else              vo[m * 64 + n - 128] = vv + bv[n - 128];
        }
    }
}

// ---------------- chunked segmented scan --------------------------------------
__global__ __launch_bounds__(64)
void scan_carry(const float* __restrict__ k, const float* __restrict__ v,
                const int* __restrict__ start,
                float* __restrict__ L, float* __restrict__ Lz, int* __restrict__ keepf)
{
    __shared__ float kbuf[CH];
    __shared__ int   sbuf[CH];
    const int c = blockIdx.x, i = blockIdx.y, j = threadIdx.x;
    const int t0 = c * CH;
    kbuf[j] = k[(size_t)(t0 + j) * Kn + i];
    sbuf[j] = start[t0 + j];
    __syncthreads();

    float run = 0.f, zr = 0.f;
    int anyst = 0;
    for (int tt = 0; tt < CH; tt++) {
        if (sbuf[tt]) { run = 0.f; zr = 0.f; anyst = 1; }
        float kt = kbuf[tt];
        run = fmaf(kt, v[(size_t)(t0 + tt) * Vn + j], run);
        zr += kt;
    }
    L[c * (Kn * Vn) + i * Vn + j] = run;
    if (j == 0) Lz[c * Kn + i] = zr;
    if (i == 0 && j == 0) keepf[c] = !anyst;
}

__global__ __launch_bounds__(1024)
void scan_combine(const float* __restrict__ s0, const float* __restrict__ z0,
                  const float* __restrict__ L, const float* __restrict__ Lz,
                  const int* __restrict__ keepf,
                  float* __restrict__ Sin, float* __restrict__ Zin)
{
    const int tid = threadIdx.x;
    float S[4];
#pragma unroll
    for (int u = 0; u < 4; u++) S[u] = s0[tid * 4 + u];
    float Z = (tid < Kn) ? z0[tid] : 0.f;

    for (int c = 0; c < NCH; c++) {
#pragma unroll
        for (int u = 0; u < 4; u++) Sin[c * (Kn * Vn) + tid * 4 + u] = S[u];
        if (tid < Kn) Zin[c * Kn + tid] = Z;
        int kp = keepf[c];
#pragma unroll
        for (int u = 0; u < 4; u++)
            S[u] = (kp ? S[u] : 0.f) + L[c * (Kn * Vn) + tid * 4 + u];
        if (tid < Kn) Z = (kp ? Z : 0.f) + Lz[c * Kn + tid];
    }
}

__global__ __launch_bounds__(64)
void scan_out(const float* __restrict__ k, const float* __restrict__ v,
              const int* __restrict__ start,
              const float* __restrict__ Sin, const float* __restrict__ Zin,
              float* __restrict__ out_s, float* __restrict__ out_z)
{
    __shared__ float kbuf[CH];
    __shared__ int   sbuf[CH];
    const int c = blockIdx.x, i = blockIdx.y, j = threadIdx.x;
    const int t0 = c * CH;
    kbuf[j] = k[(size_t)(t0 + j) * Kn + i];
    sbuf[j] = start[t0 + j];
    __syncthreads();

    float run = Sin[c * (Kn * Vn) + i * Vn + j];
    float zr  = Zin[c * Kn + i];
    for (int tt = 0; tt < CH; tt++) {
        if (sbuf[tt]) { run = 0.f; zr = 0.f; }
        float kt = kbuf[tt];
        run = fmaf(kt, v[(size_t)(t0 + tt) * Vn + j], run);
        zr += kt;
        out_s[(size_t)(t0 + tt) * (Kn * Vn) + i * Vn + j] = run;
        if (j == 0) out_z[(size_t)(t0 + tt) * Kn + i] = zr;
    }
}

// ---------------- attention output (writes bf16 att) -------------------------
__global__ __launch_bounds__(64)
void attn_kernel(const float* __restrict__ s, const float* __restrict__ z,
                 const float* __restrict__ q, __nv_bfloat16* __restrict__ outp)
{
    __shared__ float qs[64];
    __shared__ float zs[64];
    __shared__ float dsh;

    const int t = blockIdx.x, j = threadIdx.x;
    qs[j] = q[t * 64 + j];
    zs[j] = z[t * 64 + j];
    __syncthreads();
    if (j == 0) {
        float qsum = 0.f, zsum = 0.f;
        for (int i = 0; i < 64; i++) { qsum += qs[i]; zsum += zs[i]; }
        dsh = fmaxf(zsum * qsum, 1e-6f);
    }
    __syncthreads();

    float acc = 0.f;
    const float* sp = s + (size_t)t * 4096;
#pragma unroll 8
    for (int i = 0; i < 64; i++)
        acc = fmaf(sp[i * 64 + j], qs[i], acc);
    outp[t * 64 + j] = __float2bfloat16(acc / dsh);
}

// ---------------- LayerNorm over H ------------------------------------------
__global__ __launch_bounds__(256)
void ln_kernel(const float* __restrict__ h, const float* __restrict__ g,
               const float* __restrict__ b, float* __restrict__ o)
{
    __shared__ float red[256];
    const int t = blockIdx.x, tid = threadIdx.x;
    const float* hp = h + (size_t)t * Hn;

    float loc[16];
    float sum = 0.f;
#pragma unroll
    for (int u = 0; u < 16; u++) { loc[u] = hp[tid + u * 256]; sum += loc[u]; }
    red[tid] = sum; __syncthreads();
    for (int s = 128; s > 0; s >>= 1) { if (tid < s) red[tid] += red[tid + s]; __syncthreads(); }
    float mu = red[0] * (1.f / Hn);
    __syncthreads();

    float sq = 0.f;
#pragma unroll
    for (int u = 0; u < 16; u++) { float d = loc[u] - mu; sq += d * d; }
    red[tid] = sq; __syncthreads();
    for (int s = 128; s > 0; s >>= 1) { if (tid < s) red[tid] += red[tid + s]; __syncthreads(); }
    float inv = rsqrtf(red[0] * (1.f / Hn) + 1e-5f);

#pragma unroll
    for (int u = 0; u < 16; u++) {
        int idx = tid + u * 256;
        o[(size_t)t * Hn + idx] = (loc[u] - mu) * inv * g[idx] + b[idx];
    }
}

// ---------------- launch ----------------------------------------------------
extern "C" void kernel_launch(void* const* d_in, const int* in_sizes, int n_in,
                              void* d_out, int out_size)
{
    const float* x     = (const float*)d_in[0];
    const float* s0    = (const float*)d_in[1];
    const float* z0    = (const float*)d_in[2];
    const int*   start = (const int*)d_in[3];   // bool materialized as int32
    const float* Wk    = (const float*)d_in[5];
    const float* Wq    = (const float*)d_in[6];
    const float* Wv    = (const float*)d_in[7];
    const float* bv    = (const float*)d_in[8];
    const float* Wskip = (const float*)d_in[9];
    const float* bskip = (const float*)d_in[10];
    const float* W1    = (const float*)d_in[11];
    const float* b1    = (const float*)d_in[12];
    const float* W2    = (const float*)d_in[13];
    const float* b2    = (const float*)d_in[14];
    const float* W3    = (const float*)d_in[15];
    const float* b3    = (const float*)d_in[16];
    const float* ln_g  = (const float*)d_in[17];
    const float* ln_b  = (const float*)d_in[18];

    float* out    = (float*)d_out;
    float* out_hn = out;
    float* out_s  = out + (size_t)Tn * Hn;
    float* out_z  = out_s + (size_t)Tn * Kn * Vn;

    float *gk, *gq, *gv, *gh3, *gwqkv, *gL, *gSin, *gLz, *gZin;
    int* gkeep;
    __nv_bfloat16 *gattb, *gh1b, *gh2b, *gw1b, *gw2b, *gw3b, *gxh, *gwsh, *gxcat, *gwcat;
    cudaGetSymbolAddress((void**)&gk,    g_k);
    cudaGetSymbolAddress((void**)&gq,    g_q);
    cudaGetSymbolAddress((void**)&gv,    g_v);
    cudaGetSymbolAddress((void**)&gh3,   g_h3);
    cudaGetSymbolAddress((void**)&gwqkv, g_wqkv);
    cudaGetSymbolAddress((void**)&gattb, g_attb);
    cudaGetSymbolAddress((void**)&gh1b,  g_h1b);
    cudaGetSymbolAddress((void**)&gh2b,  g_h2b);
    cudaGetSymbolAddress((void**)&gw1b,  g_w1b);
    cudaGetSymbolAddress((void**)&gw2b,  g_w2b);
    cudaGetSymbolAddress((void**)&gw3b,  g_w3b);
    cudaGetSymbolAddress((void**)&gxh,   g_xh);
    cudaGetSymbolAddress((void**)&gwsh,  g_wsh);
    cudaGetSymbolAddress((void**)&gxcat, g_xcat);
    cudaGetSymbolAddress((void**)&gwcat, g_wcat);
    cudaGetSymbolAddress((void**)&gL,    g_L);
    cudaGetSymbolAddress((void**)&gSin,  g_Sin);
    cudaGetSymbolAddress((void**)&gLz,   g_Lz);
    cudaGetSymbolAddress((void**)&gZin,  g_Zin);
    cudaGetSymbolAddress((void**)&gkeep, g_keep);

    dim3 blk(256);
    auto grd = [](int M, int N) { return dim3((N + 127) / 128, (M + 127) / 128); };
    auto cgrd = [](int n) { return dim3((n + 255) / 256); };

    // concat qkv weights (device-to-device, capture-safe)
    cudaMemcpyAsync(gwqkv,             Wk, 64 * INn * 4, cudaMemcpyDeviceToDevice);
    cudaMemcpyAsync(gwqkv +  64 * INn, Wq, 64 * INn * 4, cudaMemcpyDeviceToDevice);
    cudaMemcpyAsync(gwqkv + 128 * INn, Wv, 64 * INn * 4, cudaMemcpyDeviceToDevice);

    // conversions
    f2bf<<<cgrd(Hn * Vn), blk>>>(W1, gw1b, Hn * Vn);
    f2bf<<<cgrd(Hn * Hn), blk>>>(W2, gw2b, Hn * Hn);
    f2bf<<<cgrd(Hn * Hn), blk>>>(W3, gw3b, Hn * Hn);
    split_x<<<cgrd(Tn * INn), blk>>>(x, gxh, gxcat, Tn * INn);
    split_w<<<cgrd(Hn * INn), blk>>>(Wskip, gwsh, gwcat, Hn * INn);

    // fused qkv projection (exact fp32, full chip)
    qkv_gemm<<<dim3(3, 64), blk>>>(x, gwqkv, bv, gk, gq, gv);

    // chunked segmented scan -> s,z into d_out
    scan_carry<<<dim3(NCH, Kn), 64>>>(gk, gv, start, gL, gLz, gkeep);
    scan_combine<<<1, 1024>>>(s0, z0, gL, gLz, gkeep, gSin, gZin);
    scan_out<<<dim3(NCH, Kn), 64>>>(gk, gv, start, gSin, gZin, out_s, out_z);

    // attention readout -> bf16 att
    attn_kernel<<<Tn, 64>>>(out_s, out_z, gq, gattb);

    // MLP on bf16 tensor cores
    gemm_bf16<1><<<grd(Tn, Hn), blk>>>(gattb, gw1b, b1, gh1b, Tn, Hn, Vn);
    gemm_bf16<1><<<grd(Tn, Hn), blk>>>(gh1b, gw2b, b2, gh2b, Tn, Hn, Hn);
    gemm_bf16<0><<<grd(Tn, Hn), blk>>>(gh2b, gw3b, b3, gh3, Tn, Hn, Hn);

    // skip: split-bf16, main (K=512) + merged cross terms (K=1024)
    gemm_bf16<2><<<grd(Tn, Hn), blk>>>(gxh, gwsh, bskip, gh3, Tn, Hn, INn);
    gemm_bf16<2><<<grd(Tn, Hn), blk>>>(gxcat, gwcat, nullptr, gh3, Tn, Hn, 2 * INn);

    // LayerNorm -> hn
    ln_kernel<<<Tn, 256>>>(gh3, ln_g, ln_b, out_hn);
}

// round 14
// speedup vs baseline: 4.4077x; 1.1205x over previous
#include <cuda_runtime.h>
#include <cuda_bf16.h>
#include <cstdint>
#include <math.h>

#define Tn  4096
#define INn 512
#define Kn  64
#define Vn  64
#define Hn  4096
#define CH  64
#define NCH (Tn / CH)

// ---------------- scratch (device globals; no cudaMalloc allowed) -----------
__device__ float g_k  [Tn * Kn];
__device__ float g_q  [Tn * Kn];
__device__ float g_v  [Tn * Vn];
__device__ float g_h3 [Tn * Hn];
__device__ float g_wqkv[192 * INn];
__device__ __nv_bfloat16 g_attb[Tn * Vn];
__device__ __nv_bfloat16 g_h1b [Tn * Hn];
__device__ __nv_bfloat16 g_h2b [Tn * Hn];
__device__ __nv_bfloat16 g_w1b [Hn * Vn];
__device__ __nv_bfloat16 g_w2b [(size_t)Hn * Hn];
__device__ __nv_bfloat16 g_w3b [(size_t)Hn * Hn];
__device__ __nv_bfloat16 g_xh  [Tn * INn];
__device__ __nv_bfloat16 g_wsh [Hn * INn];
__device__ __nv_bfloat16 g_xcat[(size_t)Tn * 2 * INn];
__device__ __nv_bfloat16 g_wcat[(size_t)Hn * 2 * INn];
__device__ float g_L  [NCH * Kn * Vn];
__device__ float g_Sin[NCH * Kn * Vn];
__device__ float g_Lz [NCH * Kn];
__device__ float g_Zin[NCH * Kn];
__device__ int   g_keep[NCH];

// ---------------- activations ----------------------------------------------
__device__ __forceinline__ float mishf(float x) {
    if (x > 20.f) return x;
    float u = expf(x);
    float w = u * (u + 2.f);
    return x * w / (w + 2.f);
}

// ---------------- async copy helpers ------------------------------------------
__device__ __forceinline__ void cp_async16(uint32_t saddr, const void* gaddr) {
    asm volatile("cp.async.cg.shared.global [%0], [%1], 16;\n" :: "r"(saddr), "l"(gaddr));
}
__device__ __forceinline__ void cp_commit() { asm volatile("cp.async.commit_group;\n"); }
template <int N>
__device__ __forceinline__ void cp_wait() { asm volatile("cp.async.wait_group %0;\n" :: "n"(N)); }

__device__ __forceinline__ void mma_bf16(float* d, const uint32_t* a, const uint32_t* b) {
    asm volatile(
        "mma.sync.aligned.m16n8k16.row.col.f32.bf16.bf16.f32 "
        "{%0,%1,%2,%3}, {%4,%5,%6,%7}, {%8,%9}, {%0,%1,%2,%3};\n"
        : "+f"(d[0]), "+f"(d[1]), "+f"(d[2]), "+f"(d[3])
        : "r"(a[0]), "r"(a[1]), "r"(a[2]), "r"(a[3]), "r"(b[0]), "r"(b[1]));
}

// ======================= bf16 tensor-core GEMM ================================
// C[M,N] = A[M,K] * W[N,K]^T (+bias). m16n8k16 bf16 mma, fp32 accumulate.
// 128x128 tile, K-chunks of 32, 4-STAGE cp.async pipeline (loads get 3
// iterations of slack vs the exposed-latency 2-stage version), 8 warps 64x32.
// Dynamic smem: stage s at s*20480; A rows (stride 80B) at +0, W at +10240.
// Row stride 40 bf16 -> ldmatrix row pointers hit all 32 banks (conflict-free).
#define BKB 32
#define NSTAGE 4
#define STG 20480
#define GEMM_SMEM (NSTAGE * STG)   // 81920 bytes

// EPI: 0 = fp32 store (acc+bias) ; 1 = mish(acc+bias) -> bf16 store
//      2 = fp32 accumulate (C += acc + bias)
template <int EPI>
__global__ __launch_bounds__(256)
void gemm_bf16(const __nv_bfloat16* __restrict__ A, const __nv_bfloat16* __restrict__ W,
               const float* __restrict__ bias, void* __restrict__ Cv,
               int M, int N, int K)
{
    extern __shared__ __align__(16) char smem_raw[];
    const uint32_t sb = (uint32_t)__cvta_generic_to_shared(smem_raw);

    const int tid  = threadIdx.x;
    const int lane = tid & 31;
    const int wid  = tid >> 5;
    const int g    = lane >> 2;
    const int tig  = lane & 3;
    const int wm   = (wid & 1) * 64;
    const int wn   = (wid >> 1) * 32;
    const int m0   = blockIdx.y * 128;
    const int n0   = blockIdx.x * 128;

    const int ld_row = tid & 127;
    const bool is_a  = tid < 128;
    const __nv_bfloat16* gbase = is_a ? (A + (size_t)(m0 + ld_row) * K)
                                      : (W + (size_t)(n0 + ld_row) * K);
    const uint32_t srow = (is_a ? 0u : 10240u) + (uint32_t)ld_row * 80u;

    float acc[4][4][4];
#pragma unroll
    for (int mt = 0; mt < 4; mt++)
#pragma unroll
        for (int nt = 0; nt < 4; nt++)
#pragma unroll
            for (int r = 0; r < 4; r++) acc[mt][nt][r] = 0.f;

    const int niter = K / BKB;

    // issue chunk `src` into pipeline stage `stg`
    auto issue = [&](int stg, int src) {
        uint32_t sa = sb + (uint32_t)stg * STG + srow;
        const __nv_bfloat16* gp = gbase + (size_t)src * BKB;
#pragma unroll
        for (int ch = 0; ch < 4; ch++)
            cp_async16(sa + ch * 16, gp + ch * 8);
        cp_commit();
    };

    // prologue: fill 3 stages (clamp source for tiny K)
    issue(0, 0);
    issue(1, niter > 1 ? 1 : niter - 1);
    issue(2, niter > 2 ? 2 : niter - 1);

    // ldmatrix addressing (constant per thread)
    const int a_m  = lane & 15;
    const int a_k  = (lane >> 4) * 8;
    const int b_g8 = lane >> 3;
    const int b_n  = (lane & 7) + 8 * (b_g8 >> 1);
    const int b_k  = (b_g8 & 1) * 8;

    for (int it = 0; it < niter; it++) {
        cp_wait<2>();          // group for chunk `it` complete
        __syncthreads();       // all warps past iteration it-1; stage (it+3)&3 free

        {   // keep the pipe full
            int nx = it + 3; if (nx >= niter) nx = niter - 1;
            issue((it + 3) & 3, nx);
        }

        const uint32_t stga = sb + (uint32_t)(it & 3) * STG;
        const uint32_t stgb = stga + 10240u;
#pragma unroll
        for (int kk = 0; kk < BKB; kk += 16) {
            uint32_t a[4][4], b[4][2];
#pragma unroll
            for (int mt = 0; mt < 4; mt++) {
                uint32_t sa = stga + (uint32_t)(wm + 16 * mt + a_m) * 80u
                                   + (uint32_t)(kk + a_k) * 2u;
                asm volatile("ldmatrix.sync.aligned.m8n8.x4.shared.b16 {%0,%1,%2,%3}, [%4];"
                    : "=r"(a[mt][0]), "=r"(a[mt][1]), "=r"(a[mt][2]), "=r"(a[mt][3])
                    : "r"(sa));
            }
#pragma unroll
            for (int p = 0; p < 2; p++) {
                uint32_t sbb = stgb + (uint32_t)(wn + 16 * p + b_n) * 80u
                                    + (uint32_t)(kk + b_k) * 2u;
                asm volatile("ldmatrix.sync.aligned.m8n8.x4.shared.b16 {%0,%1,%2,%3}, [%4];"
                    : "=r"(b[2 * p][0]), "=r"(b[2 * p][1]),
                      "=r"(b[2 * p + 1][0]), "=r"(b[2 * p + 1][1])
                    : "r"(sbb));
            }
#pragma unroll
            for (int mt = 0; mt < 4; mt++)
#pragma unroll
                for (int nt = 0; nt < 4; nt++)
                    mma_bf16(acc[mt][nt], a[mt], b[nt]);
        }
    }

#pragma unroll
    for (int mt = 0; mt < 4; mt++) {
#pragma unroll
        for (int nt = 0; nt < 4; nt++) {
            int r0 = m0 + wm + 16 * mt + g;
            int cc = n0 + wn + 8 * nt + 2 * tig;
            float bs0 = bias ? bias[cc]     : 0.f;
            float bs1 = bias ? bias[cc + 1] : 0.f;
            float v0 = acc[mt][nt][0] + bs0;
            float v1 = acc[mt][nt][1] + bs1;
            float v2 = acc[mt][nt][2] + bs0;
            float v3 = acc[mt][nt][3] + bs1;
            if (EPI == 1) {
                __nv_bfloat16* C = (__nv_bfloat16*)Cv;
                C[(size_t)r0 * N + cc]           = __float2bfloat16(mishf(v0));
                C[(size_t)r0 * N + cc + 1]       = __float2bfloat16(mishf(v1));
                C[(size_t)(r0 + 8) * N + cc]     = __float2bfloat16(mishf(v2));
                C[(size_t)(r0 + 8) * N + cc + 1] = __float2bfloat16(mishf(v3));
            } else if (EPI == 0) {
                float* C = (float*)Cv;
                C[(size_t)r0 * N + cc]           = v0;
                C[(size_t)r0 * N + cc + 1]       = v1;
                C[(size_t)(r0 + 8) * N + cc]     = v2;
                C[(size_t)(r0 + 8) * N + cc + 1] = v3;
            } else {
                float* C = (float*)Cv;
                C[(size_t)r0 * N + cc]           += v0;
                C[(size_t)r0 * N + cc + 1]       += v1;
                C[(size_t)(r0 + 8) * N + cc]     += v2;
                C[(size_t)(r0 + 8) * N + cc + 1] += v3;
            }
        }
    }
}

// ---------------- fp32 -> bf16 conversions -----------------------------------
__global__ void f2bf(const float* __restrict__ in, __nv_bfloat16* __restrict__ out, int n) {
    int i = blockIdx.x * 256 + threadIdx.x;
    if (i < n) out[i] = __float2bfloat16(in[i]);
}
__global__ void split_x(const float* __restrict__ in, __nv_bfloat16* __restrict__ hi,
                        __nv_bfloat16* __restrict__ cat, int n) {
    int i = blockIdx.x * 256 + threadIdx.x;
    if (i < n) {
        float v = in[i];
        __nv_bfloat16 h = __float2bfloat16(v);
        __nv_bfloat16 l = __float2bfloat16(v - __bfloat162float(h));
        int r = i / INn, c = i % INn;
        hi[i] = h;
        cat[(size_t)r * (2 * INn) + c] = h;
        cat[(size_t)r * (2 * INn) + INn + c] = l;
    }
}
__global__ void split_w(const float* __restrict__ in, __nv_bfloat16* __restrict__ hi,
                        __nv_bfloat16* __restrict__ cat, int n) {
    int i = blockIdx.x * 256 + threadIdx.x;
    if (i < n) {
        float v = in[i];
        __nv_bfloat16 h = __float2bfloat16(v);
        __nv_bfloat16 l = __float2bfloat16(v - __bfloat162float(h));
        int r = i / INn, c = i % INn;
        hi[i] = h;
        cat[(size_t)r * (2 * INn) + c] = l;
        cat[(size_t)r * (2 * INn) + INn + c] = h;
    }
}

// ---------------- fused qkv GEMM (exact fp32) ---------------------------------
__global__ __launch_bounds__(256)
void qkv_gemm(const float* __restrict__ x, const float* __restrict__ Wc,
              const float* __restrict__ bv,
              float* __restrict__ ko, float* __restrict__ qo, float* __restrict__ vo)
{
    __shared__ float As[16][64];
    __shared__ float Bs[16][64];
    const int tid = threadIdx.x;
    const int tx = tid & 15, ty = tid >> 4;
    const int m0 = blockIdx.y * 64, n0 = blockIdx.x * 64;
    const int lrow = tid >> 2, lk = (tid & 3) * 4;

    float acc[4][4];
#pragma unroll
    for (int i = 0; i < 4; i++)
#pragma unroll
        for (int j = 0; j < 4; j++) acc[i][j] = 0.f;

    for (int k0 = 0; k0 < INn; k0 += 16) {
        float4 av = *(const float4*)(x  + (size_t)(m0 + lrow) * INn + k0 + lk);
        float4 bw = *(const float4*)(Wc + (size_t)(n0 + lrow) * INn + k0 + lk);
        As[lk + 0][lrow] = av.x; As[lk + 1][lrow] = av.y;
        As[lk + 2][lrow] = av.z; As[lk + 3][lrow] = av.w;
        Bs[lk + 0][lrow] = bw.x; Bs[lk + 1][lrow] = bw.y;
        Bs[lk + 2][lrow] = bw.z; Bs[lk + 3][lrow] = bw.w;
        __syncthreads();
#pragma unroll
        for (int kk = 0; kk < 16; kk++) {
            float a[4], b[4];
#pragma unroll
            for (int u = 0; u < 4; u++) { a[u] = As[kk][ty * 4 + u]; b[u] = Bs[kk][tx * 4 + u]; }
#pragma unroll
            for (int i = 0; i < 4; i++)
#pragma unroll
                for (int j = 0; j < 4; j++)
                    acc[i][j] = fmaf(a[i], b[j], acc[i][j]);
        }
        __syncthreads();
    }

#pragma unroll
    for (int i = 0; i < 4; i++) {
        int m = m0 + ty * 4 + i;
#pragma unroll
        for (int j = 0; j < 4; j++) {
            int n = n0 + tx * 4 + j;
            float vv = acc[i][j];
            if (n < 64)       ko[m * 64 + n]       = (vv > 0.f) ? (1.f + vv) : expf(vv);
            else if (n < 128) qo[m * 64 + n - 64]  = (vv > 0.f) ? (1.f + vv) : expf(vv);
            else              vo[m * 64 + n - 128] = vv + bv[n - 128];
        }
    }
}

// ---------------- chunked segmented scan --------------------------------------
__global__ __launch_bounds__(64)
void scan_carry(const float* __restrict__ k, const float* __restrict__ v,
                const int* __restrict__ start,
                float* __restrict__ L, float* __restrict__ Lz, int* __restrict__ keepf)
{
    __shared__ float kbuf[CH];
    __shared__ int   sbuf[CH];
    const int c = blockIdx.x, i = blockIdx.y, j = threadIdx.x;
    const int t0 = c * CH;
    kbuf[j] = k[(size_t)(t0 + j) * Kn + i];
    sbuf[j] = start[t0 + j];
    __syncthreads();

    float run = 0.f, zr = 0.f;
    int anyst = 0;
    for (int tt = 0; tt < CH; tt++) {
        if (sbuf[tt]) { run = 0.f; zr = 0.f; anyst = 1; }
        float kt = kbuf[tt];
        run = fmaf(kt, v[(size_t)(t0 + tt) * Vn + j], run);
        zr += kt;
    }
    L[c * (Kn * Vn) + i * Vn + j] = run;
    if (j == 0) Lz[c * Kn + i] = zr;
    if (i == 0 && j == 0) keepf[c] = !anyst;
}

__global__ __launch_bounds__(1024)
void scan_combine(const float* __restrict__ s0, const float* __restrict__ z0,
                  const float* __restrict__ L, const float* __restrict__ Lz,
                  const int* __restrict__ keepf,
                  float* __restrict__ Sin, float* __restrict__ Zin)
{
    const int tid = threadIdx.x;
    float S[4];
#pragma unroll
    for (int u = 0; u < 4; u++) S[u] = s0[tid * 4 + u];
    float Z = (tid < Kn) ? z0[tid] : 0.f;

    for (int c = 0; c < NCH; c++) {
#pragma unroll
        for (int u = 0; u < 4; u++) Sin[c * (Kn * Vn) + tid * 4 + u] = S[u];
        if (tid < Kn) Zin[c * Kn + tid] = Z;
        int kp = keepf[c];
#pragma unroll
        for (int u = 0; u < 4; u++)
            S[u] = (kp ? S[u] : 0.f) + L[c * (Kn * Vn) + tid * 4 + u];
        if (tid < Kn) Z = (kp ? Z : 0.f) + Lz[c * Kn + tid];
    }
}

__global__ __launch_bounds__(64)
void scan_out(const float* __restrict__ k, const float* __restrict__ v,
              const int* __restrict__ start,
              const float* __restrict__ Sin, const float* __restrict__ Zin,
              float* __restrict__ out_s, float* __restrict__ out_z)
{
    __shared__ float kbuf[CH];
    __shared__ int   sbuf[CH];
    const int c = blockIdx.x, i = blockIdx.y, j = threadIdx.x;
    const int t0 = c * CH;
    kbuf[j] = k[(size_t)(t0 + j) * Kn + i];
    sbuf[j] = start[t0 + j];
    __syncthreads();

    float run = Sin[c * (Kn * Vn) + i * Vn + j];
    float zr  = Zin[c * Kn + i];
    for (int tt = 0; tt < CH; tt++) {
        if (sbuf[tt]) { run = 0.f; zr = 0.f; }
        float kt = kbuf[tt];
        run = fmaf(kt, v[(size_t)(t0 + tt) * Vn + j], run);
        zr += kt;
        out_s[(size_t)(t0 + tt) * (Kn * Vn) + i * Vn + j] = run;
        if (j == 0) out_z[(size_t)(t0 + tt) * Kn + i] = zr;
    }
}

// ---------------- attention output (writes bf16 att) -------------------------
__global__ __launch_bounds__(64)
void attn_kernel(const float* __restrict__ s, const float* __restrict__ z,
                 const float* __restrict__ q, __nv_bfloat16* __restrict__ outp)
{
    __shared__ float qs[64];
    __shared__ float zs[64];
    __shared__ float dsh;

    const int t = blockIdx.x, j = threadIdx.x;
    qs[j] = q[t * 64 + j];
    zs[j] = z[t * 64 + j];
    __syncthreads();
    if (j == 0) {
        float qsum = 0.f, zsum = 0.f;
        for (int i = 0; i < 64; i++) { qsum += qs[i]; zsum += zs[i]; }
        dsh = fmaxf(zsum * qsum, 1e-6f);
    }
    __syncthreads();

    float acc = 0.f;
    const float* sp = s + (size_t)t * 4096;
#pragma unroll 8
    for (int i = 0; i < 64; i++)
        acc = fmaf(sp[i * 64 + j], qs[i], acc);
    outp[t * 64 + j] = __float2bfloat16(acc / dsh);
}

// ---------------- LayerNorm over H ------------------------------------------
__global__ __launch_bounds__(256)
void ln_kernel(const float* __restrict__ h, const float* __restrict__ g,
               const float* __restrict__ b, float* __restrict__ o)
{
    __shared__ float red[256];
    const int t = blockIdx.x, tid = threadIdx.x;
    const float* hp = h + (size_t)t * Hn;

    float loc[16];
    float sum = 0.f;
#pragma unroll
    for (int u = 0; u < 16; u++) { loc[u] = hp[tid + u * 256]; sum += loc[u]; }
    red[tid] = sum; __syncthreads();
    for (int s = 128; s > 0; s >>= 1) { if (tid < s) red[tid] += red[tid + s]; __syncthreads(); }
    float mu = red[0] * (1.f / Hn);
    __syncthreads();

    float sq = 0.f;
#pragma unroll
    for (int u = 0; u < 16; u++) { float d = loc[u] - mu; sq += d * d; }
    red[tid] = sq; __syncthreads();
    for (int s = 128; s > 0; s >>= 1) { if (tid < s) red[tid] += red[tid + s]; __syncthreads(); }
    float inv = rsqrtf(red[0] * (1.f / Hn) + 1e-5f);

#pragma unroll
    for (int u = 0; u < 16; u++) {
        int idx = tid + u * 256;
        o[(size_t)t * Hn + idx] = (loc[u] - mu) * inv * g[idx] + b[idx];
    }
}

// ---------------- launch ----------------------------------------------------
extern "C" void kernel_launch(void* const* d_in, const int* in_sizes, int n_in,
                              void* d_out, int out_size)
{
    const float* x     = (const float*)d_in[0];
    const float* s0    = (const float*)d_in[1];
    const float* z0    = (const float*)d_in[2];
    const int*   start = (const int*)d_in[3];
    const float* Wk    = (const float*)d_in[5];
    const float* Wq    = (const float*)d_in[6];
    const float* Wv    = (const float*)d_in[7];
    const float* bv    = (const float*)d_in[8];
    const float* Wskip = (const float*)d_in[9];
    const float* bskip = (const float*)d_in[10];
    const float* W1    = (const float*)d_in[11];
    const float* b1    = (const float*)d_in[12];
    const float* W2    = (const float*)d_in[13];
    const float* b2    = (const float*)d_in[14];
    const float* W3    = (const float*)d_in[15];
    const float* b3    = (const float*)d_in[16];
    const float* ln_g  = (const float*)d_in[17];
    const float* ln_b  = (const float*)d_in[18];

    float* out    = (float*)d_out;
    float* out_hn = out;
    float* out_s  = out + (size_t)Tn * Hn;
    float* out_z  = out_s + (size_t)Tn * Kn * Vn;

    float *gk, *gq, *gv, *gh3, *gwqkv, *gL, *gSin, *gLz, *gZin;
    int* gkeep;
    __nv_bfloat16 *gattb, *gh1b, *gh2b, *gw1b, *gw2b, *gw3b, *gxh, *gwsh, *gxcat, *gwcat;
    cudaGetSymbolAddress((void**)&gk,    g_k);
    cudaGetSymbolAddress((void**)&gq,    g_q);
    cudaGetSymbolAddress((void**)&gv,    g_v);
    cudaGetSymbolAddress((void**)&gh3,   g_h3);
    cudaGetSymbolAddress((void**)&gwqkv, g_wqkv);
    cudaGetSymbolAddress((void**)&gattb, g_attb);
    cudaGetSymbolAddress((void**)&gh1b,  g_h1b);
    cudaGetSymbolAddress((void**)&gh2b,  g_h2b);
    cudaGetSymbolAddress((void**)&gw1b,  g_w1b);
    cudaGetSymbolAddress((void**)&gw2b,  g_w2b);
    cudaGetSymbolAddress((void**)&gw3b,  g_w3b);
    cudaGetSymbolAddress((void**)&gxh,   g_xh);
    cudaGetSymbolAddress((void**)&gwsh,  g_wsh);
    cudaGetSymbolAddress((void**)&gxcat, g_xcat);
    cudaGetSymbolAddress((void**)&gwcat, g_wcat);
    cudaGetSymbolAddress((void**)&gL,    g_L);
    cudaGetSymbolAddress((void**)&gSin,  g_Sin);
    cudaGetSymbolAddress((void**)&gLz,   g_Lz);
    cudaGetSymbolAddress((void**)&gZin,  g_Zin);
    cudaGetSymbolAddress((void**)&gkeep, g_keep);

    // raise dynamic smem limit for the 4-stage gemm (idempotent host calls)
    cudaFuncSetAttribute(gemm_bf16<0>, cudaFuncAttributeMaxDynamicSharedMemorySize, GEMM_SMEM);
    cudaFuncSetAttribute(gemm_bf16<1>, cudaFuncAttributeMaxDynamicSharedMemorySize, GEMM_SMEM);
    cudaFuncSetAttribute(gemm_bf16<2>, cudaFuncAttributeMaxDynamicSharedMemorySize, GEMM_SMEM);

    dim3 blk(256);
    auto grd = [](int M, int N) { return dim3(N / 128, M / 128); };
    auto cgrd = [](int n) { return dim3((n + 255) / 256); };

    cudaMemcpyAsync(gwqkv,             Wk, 64 * INn * 4, cudaMemcpyDeviceToDevice);
    cudaMemcpyAsync(gwqkv +  64 * INn, Wq, 64 * INn * 4, cudaMemcpyDeviceToDevice);
    cudaMemcpyAsync(gwqkv + 128 * INn, Wv, 64 * INn * 4, cudaMemcpyDeviceToDevice);

    f2bf<<<cgrd(Hn * Vn), blk>>>(W1, gw1b, Hn * Vn);
    f2bf<<<cgrd(Hn * Hn), blk>>>(W2, gw2b, Hn * Hn);
    f2bf<<<cgrd(Hn * Hn), blk>>>(W3, gw3b, Hn * Hn);
    split_x<<<cgrd(Tn * INn), blk>>>(x, gxh, gxcat, Tn * INn);
    split_w<<<cgrd(Hn * INn), blk>>>(Wskip, gwsh, gwcat, Hn * INn);

    qkv_gemm<<<dim3(3, 64), blk>>>(x, gwqkv, bv, gk, gq, gv);

    scan_carry<<<dim3(NCH, Kn), 64>>>(gk, gv, start, gL, gLz, gkeep);
    scan_combine<<<1, 1024>>>(s0, z0, gL, gLz, gkeep, gSin, gZin);
    scan_out<<<dim3(NCH, Kn), 64>>>(gk, gv, start, gSin, gZin, out_s, out_z);

    attn_kernel<<<Tn, 64>>>(out_s, out_z, gq, gattb);

    // MLP on bf16 tensor cores (4-stage pipelined)
    gemm_bf16<1><<<grd(Tn, Hn), blk, GEMM_SMEM>>>(gattb, gw1b, b1, gh1b, Tn, Hn, Vn);
    gemm_bf16<1><<<grd(Tn, Hn), blk, GEMM_SMEM>>>(gh1b, gw2b, b2, gh2b, Tn, Hn, Hn);
    gemm_bf16<0><<<grd(Tn, Hn), blk, GEMM_SMEM>>>(gh2b, gw3b, b3, gh3, Tn, Hn, Hn);

    // skip: split-bf16, main (K=512) + merged cross terms (K=1024)
    gemm_bf16<2><<<grd(Tn, Hn), blk, GEMM_SMEM>>>(gxh, gwsh, bskip, gh3, Tn, Hn, INn);
    gemm_bf16<2><<<grd(Tn, Hn), blk, GEMM_SMEM>>>(gxcat, gwcat, nullptr, gh3, Tn, Hn, 2 * INn);

    ln_kernel<<<Tn, 256>>>(gh3, ln_g, ln_b, out_hn);
}